// round 14
// baseline (speedup 1.0000x reference)
#include <cuda_runtime.h>
#include <cuda_bf16.h>
#include <cuda_fp16.h>
#include <cstdint>
#include <cstddef>

#define NB 8
#define NT 8192
#define ND 128
#define NS 128
#define CK 64
#define NC (NT / CK)   // 128

// Scratch (fp16). g_p/g_hl are [b][chunk][s][t] (s-major). g_C is [b][t][s].
__device__ __half g_hl[(size_t)NB * NT * NS];
__device__ __half g_p [(size_t)NB * NT * NS];
__device__ __half g_C [(size_t)NB * NT * NS];
__device__ float  g_h0[(size_t)NB * NC * NS];
// Pre-swizzled bf16 hi/lo tiles: [mat(dt,B,C,out)][term(hi,lo)][khalf] 128r x 64k (16KB)
__device__ __align__(16) unsigned char g_Wb[4 * 2 * 2 * 16384];

__device__ __forceinline__ uint32_t smem_u32(const void* p) {
    uint32_t a;
    asm("{ .reg .u64 t; cvta.to.shared.u64 t, %1; cvt.u32.u64 %0, t; }" : "=r"(a) : "l"(p));
    return a;
}
__device__ __forceinline__ uint32_t sw128(uint32_t off) { return off ^ ((off >> 3) & 0x70); }

__device__ __forceinline__ void cp_async16(uint32_t dst, const void* src) {
    asm volatile("cp.async.cg.shared.global [%0], [%1], 16;" :: "r"(dst), "l"(src));
}
#define CP_COMMIT() asm volatile("cp.async.commit_group;" ::: "memory")
#define CP_WAIT(n)  asm volatile("cp.async.wait_group %0;" :: "n"(n) : "memory")

__device__ __forceinline__ void ldsm_x4(uint32_t* r, uint32_t addr) {
    asm volatile("ldmatrix.sync.aligned.m8n8.x4.shared.b16 {%0,%1,%2,%3}, [%4];"
        : "=r"(r[0]), "=r"(r[1]), "=r"(r[2]), "=r"(r[3]) : "r"(addr));
}
__device__ __forceinline__ void mma_bf16(float* d, const uint32_t* a, const uint32_t* b) {
    asm volatile("mma.sync.aligned.m16n8k16.row.col.f32.bf16.bf16.f32 "
        "{%0,%1,%2,%3}, {%4,%5,%6,%7}, {%8,%9}, {%0,%1,%2,%3};"
        : "+f"(d[0]), "+f"(d[1]), "+f"(d[2]), "+f"(d[3])
        : "r"(a[0]), "r"(a[1]), "r"(a[2]), "r"(a[3]), "r"(b[0]), "r"(b[1]));
}

// Inclusive pair-prefix over the 4-lane quad (width=4 groups = same dr)
__device__ __forceinline__ float quadscan(float v, int j4) {
    float t1 = __shfl_up_sync(0xFFFFFFFFu, v, 1, 4); if (j4 >= 1) v += t1;
    float t2 = __shfl_up_sync(0xFFFFFFFFu, v, 2, 4); if (j4 >= 2) v += t2;
    return v;
}

// ---------------------------------------------------------------------------
// Prep: convert 4 weight mats to swizzled bf16 hi/lo k-half tiles in global.
// ---------------------------------------------------------------------------
__global__ void prep_kernel(const float* __restrict__ W_B,
                            const float* __restrict__ W_C,
                            const float* __restrict__ W_dt,
                            const float* __restrict__ W_out)
{
    int e = blockIdx.x * 256 + threadIdx.x;
    if (e >= 4 * 16384) return;
    int mat = e >> 14, rk = e & 16383, r = rk >> 7, k = rk & 127;
    const float* W = (mat == 0) ? W_dt : (mat == 1) ? W_B : (mat == 2) ? W_C : W_out;
    float w = W[rk];
    __nv_bfloat16 hi = __float2bfloat16(w);
    __nv_bfloat16 lo = __float2bfloat16(w - __bfloat162float(hi));
    int half = k >> 6, kl = k & 63;
    uint32_t off = sw128((uint32_t)(r * 128 + kl * 2));
    *(__nv_bfloat16*)&g_Wb[((mat * 2 + 0) * 2 + half) * 16384 + off] = hi;
    *(__nv_bfloat16*)&g_Wb[((mat * 2 + 1) * 2 + half) * 16384 + off] = lo;
}

// ---------------------------------------------------------------------------
// Pass 1 (HMMA, 256 thr, 2 CTAs/SM, 96KB): 3 paired-mat W stages
// (dt&B hi -> dt&B lo -> C hi+lo), B-fragments shared across 2 mats;
// in-register quad-shuffle scan; fp16 scratch stores.
// smem: X 32KB (both terms) | W 64KB (2 tiles of current stage)
// ---------------------------------------------------------------------------
#define SM_X   0
#define SM_W   32768
#define SMEM1_BYTES 98304

__global__ __launch_bounds__(256, 2)
void pass1_mma(const float* __restrict__ x,
               const float* __restrict__ log_A,
               const float* __restrict__ b_dt)
{
    extern __shared__ unsigned char smraw[];
    const uint32_t sbase = smem_u32(smraw);
    const int c = blockIdx.x, b = blockIdx.y, tid = threadIdx.x;
    const int wid = tid >> 5, lane = tid & 31;

    // Stage two 32KB (mat,term) W tiles into SM_W / SM_W+32768
    auto stage2 = [&](int tile0, int tile1) {
#pragma unroll
        for (int j = 0; j < 16; ++j) {
            int idx = tid + 256 * j;              // 4096 x 16B = 64KB
            int hsel = idx >> 11, rem = idx & 2047;
            const unsigned char* src =
                g_Wb + (size_t)(hsel ? tile1 : tile0) * 32768 + (size_t)rem * 16;
            cp_async16(sbase + SM_W + (uint32_t)idx * 16, src);
        }
        CP_COMMIT();
    };

    stage2(0, 2);   // dt_hi (tile 0), B_hi (tile 2)

    // Convert X chunk (64 tok x 128) to bf16 hi/lo swizzled tiles
    {
        const float4* xg = (const float4*)(x + ((size_t)b * NT + (size_t)c * CK) * ND);
        unsigned char* sX = smraw + SM_X;
#pragma unroll
        for (int j = 0; j < 8; ++j) {
            int idx = tid + 256 * j;                 // 2048 float4
            float4 v = xg[idx];
            int token = idx >> 5, k4 = idx & 31;
            int half = k4 >> 4;
            uint32_t off = (uint32_t)(token * 128) +
                           (((uint32_t)(k4 & 15) * 8) ^ ((uint32_t)(token & 7) << 4));
            __nv_bfloat162 h01 = __float22bfloat162_rn(make_float2(v.x, v.y));
            __nv_bfloat162 h23 = __float22bfloat162_rn(make_float2(v.z, v.w));
            __nv_bfloat162 l01 = __float22bfloat162_rn(make_float2(
                v.x - __bfloat162float(h01.x), v.y - __bfloat162float(h01.y)));
            __nv_bfloat162 l23 = __float22bfloat162_rn(make_float2(
                v.z - __bfloat162float(h23.x), v.w - __bfloat162float(h23.y)));
            *(__nv_bfloat162*)(sX + half * 8192 + off)             = h01;
            *(__nv_bfloat162*)(sX + half * 8192 + off + 4)         = h23;
            *(__nv_bfloat162*)(sX + 16384 + half * 8192 + off)     = l01;
            *(__nv_bfloat162*)(sX + 16384 + half * 8192 + off + 4) = l23;
        }
    }

    // ldmatrix addressing (warp = m-tile rows s0..s0+15, all 64 tokens)
    const int s0 = wid * 16;
    const uint32_t ar = lane & 7, aj = lane >> 3;
    const uint32_t a_rb  = (uint32_t)(s0 + (aj & 1) * 8 + ar) * 128;
    const uint32_t a_k16 = (aj >> 1) * 16;
    const uint32_t a_xor = ar << 4;
    const uint32_t b_row = lane & 7, b_j = lane >> 3;
    const uint32_t b_off = (b_j >> 1) * 1024 + b_row * 128;
    const uint32_t b_k16 = (b_j & 1) * 16;
    const uint32_t b_xor = b_row << 4;

    // Two-mat pass: shared B fragments, per-kt A frags from both W tiles
    auto mma2 = [&](float (*acc0)[4], float (*acc1)[4], int ntb) {
        for (int tb = 0; tb < ntb; ++tb) {
#pragma unroll
            for (int kt = 0; kt < 8; ++kt) {
                const uint32_t half = kt >> 2;
                const uint32_t klo2 = (kt & 3) * 32;
                const uint32_t xb = sbase + SM_X + (uint32_t)tb * 16384 + half * 8192;
                const uint32_t wa = ((klo2 + a_k16) ^ a_xor) + a_rb + half * 16384;
                uint32_t a0[4], a1[4];
                ldsm_x4(a0, sbase + SM_W + wa);
                ldsm_x4(a1, sbase + SM_W + 32768 + wa);
#pragma unroll
                for (int i = 0; i < 4; ++i) {
                    uint32_t bfr[4];
                    ldsm_x4(bfr, xb + i * 2048 + b_off + ((klo2 + b_k16) ^ b_xor));
                    mma_bf16(acc0[2 * i],     a0, &bfr[0]);
                    mma_bf16(acc0[2 * i + 1], a0, &bfr[2]);
                    mma_bf16(acc1[2 * i],     a1, &bfr[0]);
                    mma_bf16(acc1[2 * i + 1], a1, &bfr[2]);
                }
            }
        }
    };

    float accDt[8][4], accB[8][4];
#pragma unroll
    for (int nt = 0; nt < 8; ++nt)
#pragma unroll
        for (int q = 0; q < 4; ++q) { accDt[nt][q] = 0.f; accB[nt][q] = 0.f; }

    // Stage A: (dt_hi, B_hi) x (X_hi, X_lo)
    CP_WAIT(0); __syncthreads();
    mma2(accDt, accB, 2);
    __syncthreads();
    stage2(1, 3);   // dt_lo, B_lo
    // Stage B: (dt_lo, B_lo) x X_hi
    CP_WAIT(0); __syncthreads();
    mma2(accDt, accB, 1);
    __syncthreads();
    stage2(4, 5);   // C_hi, C_lo  (overlaps with the scan below)

    // ---- In-register clipped scan ----
    {
        const int dr = lane >> 2, j4 = lane & 3, dc2 = j4 * 2;
        const int sr0 = s0 + dr, sr1 = sr0 + 8;
        const float A0 = -fminf(__expf(__ldg(log_A + sr0)), 10.0f);
        const float A1 = -fminf(__expf(__ldg(log_A + sr1)), 10.0f);
        const float bd0 = __ldg(b_dt + sr0), bd1 = __ldg(b_dt + sr1);
        const size_t pb = (((size_t)b * NC + c) * NS) * (size_t)CK;
        __half* gp0 = g_p  + pb + (size_t)sr0 * CK;
        __half* gp1 = g_p  + pb + (size_t)sr1 * CK;
        __half* gh0 = g_hl + pb + (size_t)sr0 * CK;
        __half* gh1 = g_hl + pb + (size_t)sr1 * CK;
        float cla0 = 0.f, cw0 = 0.f, cla1 = 0.f, cw1 = 0.f;
#pragma unroll
        for (int nt = 0; nt < 8; ++nt) {
            const int t0 = nt * 8 + dc2;
#pragma unroll
            for (int rr = 0; rr < 2; ++rr) {
                const float A_s = rr ? A1 : A0;
                const float bd  = rr ? bd1 : bd0;
                float& cla = rr ? cla1 : cla0;
                float& cw  = rr ? cw1  : cw0;
                float d0 = accDt[nt][rr * 2 + 0] + bd;
                float d1 = accDt[nt][rr * 2 + 1] + bd;
                float sp0 = (d0 > 15.0f) ? d0 : __logf(1.0f + __expf(d0));
                float sp1 = (d1 > 15.0f) ? d1 : __logf(1.0f + __expf(d1));
                float dt0 = fminf(sp0, 1.0f), dt1 = fminf(sp1, 1.0f);
                float la0 = fminf(fmaxf(dt0 * A_s, -0.5f), 0.0f);
                float la1 = fminf(fmaxf(dt1 * A_s, -0.5f), 0.0f);
                float u0 = accB[nt][rr * 2 + 0] * dt0;
                float u1 = accB[nt][rr * 2 + 1] * dt1;
                float xs = quadscan(la0 + la1, j4);
                float cs1 = cla + xs, cs0 = cs1 - la1;
                cla += __shfl_sync(0xFFFFFFFFu, xs, 3, 4);
                float lp0 = fminf(fmaxf(cs0, -30.0f), 0.0f);
                float lp1 = fminf(fmaxf(cs1, -30.0f), 0.0f);
                float p0 = __expf(lp0), p1 = __expf(lp1);
                float w0 = u0 * __expf(-lp0), w1 = u1 * __expf(-lp1);
                float xw = quadscan(w0 + w1, j4);
                float a1v = cw + xw, a0v = a1v - w1;
                cw += __shfl_sync(0xFFFFFFFFu, xw, 3, 4);
                __half2 pp = __floats2half2_rn(p0, p1);
                __half2 hh = __floats2half2_rn(p0 * a0v, p1 * a1v);
                if (rr == 0) { *(__half2*)&gp0[t0] = pp; *(__half2*)&gh0[t0] = hh; }
                else         { *(__half2*)&gp1[t0] = pp; *(__half2*)&gh1[t0] = hh; }
            }
        }
    }

    // ---- C projection: C_hi x (X_hi, X_lo) + C_lo x X_hi ----
    float accC[8][4];
#pragma unroll
    for (int nt = 0; nt < 8; ++nt)
#pragma unroll
        for (int q = 0; q < 4; ++q) accC[nt][q] = 0.f;

    CP_WAIT(0); __syncthreads();
    for (int tb = 0; tb < 2; ++tb) {
#pragma unroll
        for (int kt = 0; kt < 8; ++kt) {
            const uint32_t half = kt >> 2;
            const uint32_t klo2 = (kt & 3) * 32;
            const uint32_t xb = sbase + SM_X + (uint32_t)tb * 16384 + half * 8192;
            const uint32_t wa = ((klo2 + a_k16) ^ a_xor) + a_rb + half * 16384;
            uint32_t aH[4];
            ldsm_x4(aH, sbase + SM_W + wa);
            uint32_t aL[4];
            if (tb == 0) ldsm_x4(aL, sbase + SM_W + 32768 + wa);
#pragma unroll
            for (int i = 0; i < 4; ++i) {
                uint32_t bfr[4];
                ldsm_x4(bfr, xb + i * 2048 + b_off + ((klo2 + b_k16) ^ b_xor));
                mma_bf16(accC[2 * i],     aH, &bfr[0]);
                mma_bf16(accC[2 * i + 1], aH, &bfr[2]);
                if (tb == 0) {
                    mma_bf16(accC[2 * i],     aL, &bfr[0]);
                    mma_bf16(accC[2 * i + 1], aL, &bfr[2]);
                }
            }
        }
    }

    // store C in [t][s] layout (fp16 scalars)
    {
        const int dr = lane >> 2, dc2 = (lane & 3) * 2;
        const int sr0 = s0 + dr, sr1 = sr0 + 8;
        const size_t gbC = ((size_t)b * NT + (size_t)c * CK) * NS;
#pragma unroll
        for (int nt = 0; nt < 8; ++nt) {
            const int t0 = nt * 8 + dc2;
            g_C[gbC + (size_t)t0 * NS + sr0]       = __float2half(accC[nt][0]);
            g_C[gbC + (size_t)(t0 + 1) * NS + sr0] = __float2half(accC[nt][1]);
            g_C[gbC + (size_t)t0 * NS + sr1]       = __float2half(accC[nt][2]);
            g_C[gbC + (size_t)(t0 + 1) * NS + sr1] = __float2half(accC[nt][3]);
        }
    }
}

// ---------------------------------------------------------------------------
// Pass 2: inter-chunk prefix scan (fp16 tails from [s][t] layout)
// ---------------------------------------------------------------------------
#define SMEM2_BYTES (2 * 128 * 128 * 4)

__global__ __launch_bounds__(128)
void pass2_kernel()
{
    extern __shared__ float smf[];
    float* sP = smf;
    float* sH = smf + 128 * 128;
    const int b = blockIdx.x, tid = threadIdx.x;

    for (int i = tid; i < 128 * 128; i += 128) {
        int c = i >> 7, s = i & 127;
        size_t gi = (((size_t)b * NC + c) * NS + s) * (size_t)CK + (CK - 1);
        sP[i] = __half2float(g_p[gi]);
        sH[i] = __half2float(g_hl[gi]);
    }
    __syncthreads();

    const int s = tid;
    float h0 = 0.0f;
    const size_t hb = (size_t)b * NC * NS + s;
#pragma unroll 8
    for (int c = 0; c < NC; ++c) {
        g_h0[hb + (size_t)c * NS] = h0;
        h0 = fmaf(sP[c * 128 + s], h0, sH[c * 128 + s]);
    }
}

// ---------------------------------------------------------------------------
// Pass 3 (HMMA, 256 thr, 2 CTAs/SM): fp16 scratch reads; shf[s][65] fp32;
// bf16 hi/lo tiles; fp32 y-dot; 3-term MMA; epilogue overlays W/H regions.
// ---------------------------------------------------------------------------
#define P3_W 0
#define P3_H 32768
#define P3_F 65536
#define P3FS 65
#define P3S  132
#define P3_Y (65536 + 128 * P3FS * 4)
#define SMEM3_BYTES (P3_Y + 1024)

__global__ __launch_bounds__(256, 2)
void pass3_mma(const float* __restrict__ x,
               float* __restrict__ out)
{
    extern __shared__ unsigned char smraw[];
    const uint32_t sbase = smem_u32(smraw);
    float* shf = (float*)(smraw + P3_F);      // [s][65]
    float* sy  = (float*)(smraw + P3_Y);
    float* sh0 = sy + 64;
    float* sx0 = sh0 + 128;
    const int c = blockIdx.x, b = blockIdx.y, tid = threadIdx.x;
    const int wid = tid >> 5, lane = tid & 31;
    const size_t tbase = (size_t)b * NT + (size_t)c * CK;
    const size_t gbase = tbase * NS;

    // cp.async stage W_out_hi (32KB)
    {
#pragma unroll
        for (int j = 0; j < 8; ++j) {
            int idx = tid + 256 * j;
            cp_async16(sbase + P3_W + (uint32_t)idx * 16,
                       g_Wb + (size_t)3 * 65536 + (size_t)idx * 16);
        }
        CP_COMMIT();
    }
    if (tid < 128) sh0[tid] = g_h0[((size_t)b * NC + c) * NS + tid];
    else if (tid < 192) sx0[tid - 128] = x[(tbase + tid - 128) * ND];
    __syncthreads();

    // Loop1: h = hl + p*h0 -> shf[s][65]  (coalesced fp16 [s][t] reads,
    // scalar smem stores: stride-65 base is odd for odd s)
    {
        const size_t pb = (((size_t)b * NC + c) * NS) * (size_t)CK;
#pragma unroll
        for (int j = 0; j < 16; ++j) {
            int idx = tid + 256 * j;          // 4096 half2
            int s = idx >> 5, tp = idx & 31;
            int t0 = tp * 2;
            float2 pv = __half22float2(*(const __half2*)&g_p [pb + (size_t)s * CK + t0]);
            float2 hv = __half22float2(*(const __half2*)&g_hl[pb + (size_t)s * CK + t0]);
            float h0s = sh0[s];
            shf[s * P3FS + t0]     = fmaf(pv.x, h0s, hv.x);
            shf[s * P3FS + t0 + 1] = fmaf(pv.y, h0s, hv.y);
        }
    }
    __syncthreads();

    // Loop2: shf -> bf16 hi/lo swizzled tiles (token-row x s-k)
    {
        unsigned char* sH = smraw + P3_H;
#pragma unroll
        for (int j = 0; j < 32; ++j) {
            int idx = tid + 256 * j;          // 8192 elements
            int t = idx >> 7, s = idx & 127;
            float h = shf[s * P3FS + t];
            __nv_bfloat16 hi = __float2bfloat16(h);
            __nv_bfloat16 lo = __float2bfloat16(h - __bfloat162float(hi));
            int half = s >> 6, kl = s & 63;
            uint32_t off = (uint32_t)(t * 128) + (((uint32_t)kl * 2) ^ ((uint32_t)(t & 7) << 4));
            *(__nv_bfloat16*)(sH + half * 8192 + off)         = hi;
            *(__nv_bfloat16*)(sH + 16384 + half * 8192 + off) = lo;
        }
    }
    __syncthreads();

    // y[t] = sum_s C[t][s]*h[s][t]  (8 warps x 8 tokens, fp32 accum, half2 C)
    {
        for (int t = wid * 8; t < wid * 8 + 8; ++t) {
            float v = 0.0f;
#pragma unroll
            for (int q = 0; q < 2; ++q) {
                int s = 2 * lane + 64 * q;
                float2 cf = __half22float2(
                    *(const __half2*)&g_C[gbase + (size_t)t * NS + s]);
                v = fmaf(cf.x, shf[s * P3FS + t], v);
                v = fmaf(cf.y, shf[(s + 1) * P3FS + t], v);
            }
#pragma unroll
            for (int o = 16; o; o >>= 1) v += __shfl_xor_sync(0xFFFFFFFFu, v, o);
            if (lane == 0) sy[t] = v;
        }
    }
    CP_WAIT(0); __syncthreads();

    // MMA: D[d][t] = W_out h^T, one m16 tile per warp
    const int d0 = wid * 16;
    const uint32_t ar = lane & 7, aj = lane >> 3;
    const uint32_t a_rb  = (uint32_t)(d0 + (aj & 1) * 8 + ar) * 128;
    const uint32_t a_k16 = (aj >> 1) * 16;
    const uint32_t a_xor = ar << 4;
    const uint32_t b_row = lane & 7, b_j = lane >> 3;
    const uint32_t b_off = (b_j >> 1) * 1024 + b_row * 128;
    const uint32_t b_k16 = (b_j & 1) * 16;
    const uint32_t b_xor = b_row << 4;

    float acc[8][4];
#pragma unroll
    for (int nt = 0; nt < 8; ++nt)
#pragma unroll
        for (int q = 0; q < 4; ++q) acc[nt][q] = 0.0f;

    auto run_terms3 = [&](int ntb) {
        for (int tb = 0; tb < ntb; ++tb) {
#pragma unroll
            for (int kt = 0; kt < 8; ++kt) {
                const uint32_t half = kt >> 2;
                const uint32_t klo2 = (kt & 3) * 32;
                const uint32_t xb = sbase + P3_H + (uint32_t)tb * 16384 + half * 8192;
                const uint32_t wb = sbase + P3_W + half * 16384;
                uint32_t a0[4];
                ldsm_x4(a0, wb + a_rb + ((klo2 + a_k16) ^ a_xor));
#pragma unroll
                for (int i = 0; i < 4; ++i) {
                    uint32_t bfr[4];
                    ldsm_x4(bfr, xb + i * 2048 + b_off + ((klo2 + b_k16) ^ b_xor));
                    mma_bf16(acc[2 * i],     a0, &bfr[0]);
                    mma_bf16(acc[2 * i + 1], a0, &bfr[2]);
                }
            }
        }
    };

    run_terms3(2);              // W_hi x (H_hi, H_lo)
    __syncthreads();
    {                            // restage W_lo
#pragma unroll
        for (int j = 0; j < 8; ++j) {
            int idx = tid + 256 * j;
            cp_async16(sbase + P3_W + (uint32_t)idx * 16,
                       g_Wb + (size_t)3 * 65536 + 32768 + (size_t)idx * 16);
        }
        CP_COMMIT();
        CP_WAIT(0);
    }
    __syncthreads();
    run_terms3(1);              // W_lo x H_hi
    __syncthreads();            // W/H reads done -> regions reusable for out

    // fragments -> sOut[t][132] overlaying W/H regions
    {
        float* sOut = (float*)smraw;
        const int dr = lane >> 2, dc = (lane & 3) * 2;
        const int d = d0 + dr;
#pragma unroll
        for (int nt = 0; nt < 8; ++nt) {
            const int t0 = nt * 8 + dc;
            sOut[t0 * P3S + d]           = acc[nt][0];
            sOut[(t0 + 1) * P3S + d]     = acc[nt][1];
            sOut[t0 * P3S + d + 8]       = acc[nt][2];
            sOut[(t0 + 1) * P3S + d + 8] = acc[nt][3];
        }
    }
    __syncthreads();

    // Epilogue: out = staged + y[t]*x[t,0], coalesced float4
    {
        const float* sOut = (const float*)smraw;
        float4* og = (float4*)(out + gbase);
#pragma unroll
        for (int j = 0; j < 8; ++j) {
            int i4 = tid + 256 * j;          // 2048 float4
            int t = i4 >> 5, d4 = i4 & 31;
            float4 v = *(const float4*)&sOut[t * P3S + d4 * 4];
            float yv = sy[t] * sx0[t];
            v.x += yv; v.y += yv; v.z += yv; v.w += yv;
            og[i4] = v;
        }
    }
}

// ---------------------------------------------------------------------------
extern "C" void kernel_launch(void* const* d_in, const int* in_sizes, int n_in,
                              void* d_out, int out_size)
{
    const float* x     = (const float*)d_in[0];
    const float* log_A = (const float*)d_in[1];
    const float* W_B   = (const float*)d_in[2];
    const float* W_C   = (const float*)d_in[3];
    const float* W_dt  = (const float*)d_in[4];
    const float* b_dt  = (const float*)d_in[5];
    const float* W_out = (const float*)d_in[6];
    float* out = (float*)d_out;

    cudaFuncSetAttribute(pass1_mma, cudaFuncAttributeMaxDynamicSharedMemorySize, SMEM1_BYTES);
    cudaFuncSetAttribute(pass2_kernel, cudaFuncAttributeMaxDynamicSharedMemorySize, SMEM2_BYTES);
    cudaFuncSetAttribute(pass3_mma, cudaFuncAttributeMaxDynamicSharedMemorySize, SMEM3_BYTES);

    prep_kernel<<<256, 256>>>(W_B, W_C, W_dt, W_out);
    pass1_mma<<<dim3(NC, NB), 256, SMEM1_BYTES>>>(x, log_A, b_dt);
    pass2_kernel<<<NB, 128, SMEM2_BYTES>>>();
    pass3_mma<<<dim3(NC, NB), 256, SMEM3_BYTES>>>(x, out);
}

// round 15
// speedup vs baseline: 1.1403x; 1.1403x over previous
#include <cuda_runtime.h>
#include <cuda_bf16.h>
#include <cuda_fp16.h>
#include <cstdint>
#include <cstddef>

#define NB 8
#define NT 8192
#define ND 128
#define NS 128
#define CK 64
#define NC (NT / CK)   // 128

// Scratch (fp16). g_p/g_hl are [b][chunk][s][t] (s-major). g_C is [b][t][s].
__device__ __half g_hl[(size_t)NB * NT * NS];
__device__ __half g_p [(size_t)NB * NT * NS];
__device__ __half g_C [(size_t)NB * NT * NS];
__device__ float  g_h0[(size_t)NB * NC * NS];
__device__ float  g_tp[(size_t)NB * NC * NS];   // chunk tail p   (fp32, compact)
__device__ float  g_th[(size_t)NB * NC * NS];   // chunk tail hl  (fp32, compact)
// Pre-swizzled bf16 hi/lo tiles: [mat(dt,B,C,out)][term(hi,lo)][khalf] 128r x 64k (16KB)
__device__ __align__(16) unsigned char g_Wb[4 * 2 * 2 * 16384];

__device__ __forceinline__ uint32_t smem_u32(const void* p) {
    uint32_t a;
    asm("{ .reg .u64 t; cvta.to.shared.u64 t, %1; cvt.u32.u64 %0, t; }" : "=r"(a) : "l"(p));
    return a;
}
__device__ __forceinline__ uint32_t sw128(uint32_t off) { return off ^ ((off >> 3) & 0x70); }

__device__ __forceinline__ void cp_async16(uint32_t dst, const void* src) {
    asm volatile("cp.async.cg.shared.global [%0], [%1], 16;" :: "r"(dst), "l"(src));
}
#define CP_COMMIT() asm volatile("cp.async.commit_group;" ::: "memory")
#define CP_WAIT(n)  asm volatile("cp.async.wait_group %0;" :: "n"(n) : "memory")

__device__ __forceinline__ void ldsm_x4(uint32_t* r, uint32_t addr) {
    asm volatile("ldmatrix.sync.aligned.m8n8.x4.shared.b16 {%0,%1,%2,%3}, [%4];"
        : "=r"(r[0]), "=r"(r[1]), "=r"(r[2]), "=r"(r[3]) : "r"(addr));
}
__device__ __forceinline__ void mma_bf16(float* d, const uint32_t* a, const uint32_t* b) {
    asm volatile("mma.sync.aligned.m16n8k16.row.col.f32.bf16.bf16.f32 "
        "{%0,%1,%2,%3}, {%4,%5,%6,%7}, {%8,%9}, {%0,%1,%2,%3};"
        : "+f"(d[0]), "+f"(d[1]), "+f"(d[2]), "+f"(d[3])
        : "r"(a[0]), "r"(a[1]), "r"(a[2]), "r"(a[3]), "r"(b[0]), "r"(b[1]));
}

// Inclusive pair-prefix over the 4-lane quad (width=4 groups = same dr)
__device__ __forceinline__ float quadscan(float v, int j4) {
    float t1 = __shfl_up_sync(0xFFFFFFFFu, v, 1, 4); if (j4 >= 1) v += t1;
    float t2 = __shfl_up_sync(0xFFFFFFFFu, v, 2, 4); if (j4 >= 2) v += t2;
    return v;
}

// ---------------------------------------------------------------------------
// Prep: convert 4 weight mats to swizzled bf16 hi/lo k-half tiles in global.
// ---------------------------------------------------------------------------
__global__ void prep_kernel(const float* __restrict__ W_B,
                            const float* __restrict__ W_C,
                            const float* __restrict__ W_dt,
                            const float* __restrict__ W_out)
{
    int e = blockIdx.x * 256 + threadIdx.x;
    if (e >= 4 * 16384) return;
    int mat = e >> 14, rk = e & 16383, r = rk >> 7, k = rk & 127;
    const float* W = (mat == 0) ? W_dt : (mat == 1) ? W_B : (mat == 2) ? W_C : W_out;
    float w = W[rk];
    __nv_bfloat16 hi = __float2bfloat16(w);
    __nv_bfloat16 lo = __float2bfloat16(w - __bfloat162float(hi));
    int half = k >> 6, kl = k & 63;
    uint32_t off = sw128((uint32_t)(r * 128 + kl * 2));
    *(__nv_bfloat16*)&g_Wb[((mat * 2 + 0) * 2 + half) * 16384 + off] = hi;
    *(__nv_bfloat16*)&g_Wb[((mat * 2 + 1) * 2 + half) * 16384 + off] = lo;
}

// ---------------------------------------------------------------------------
// Pass 1 (HMMA, 256 thr, 2 CTAs/SM, 96KB): 6 cp.async-pipelined 32KB W stages
// (dt_hi, dt_lo, B_hi, B_lo, C_hi, C_lo; double-buffered -> always overlapped).
// Scan in fragment registers; fp16 scratch stores + fp32 compact tails.
// ---------------------------------------------------------------------------
#define SM_X   0
#define SM_W0  32768
#define SM_W1  65536
#define SMEM1_BYTES 98304

__global__ __launch_bounds__(256, 2)
void pass1_mma(const float* __restrict__ x,
               const float* __restrict__ log_A,
               const float* __restrict__ b_dt)
{
    extern __shared__ unsigned char smraw[];
    const uint32_t sbase = smem_u32(smraw);
    const int c = blockIdx.x, b = blockIdx.y, tid = threadIdx.x;
    const int wid = tid >> 5, lane = tid & 31;

    auto stage_issue = [&](int sid, uint32_t dstoff) {
        const unsigned char* src = g_Wb + (size_t)sid * 32768;
#pragma unroll
        for (int j = 0; j < 8; ++j) {
            int idx = tid + 256 * j;     // 2048 x 16B = 32KB
            cp_async16(sbase + dstoff + (uint32_t)idx * 16, src + (size_t)idx * 16);
        }
        CP_COMMIT();
    };

    stage_issue(0, SM_W0);

    // Convert X chunk (64 tok x 128) to bf16 hi/lo swizzled tiles
    {
        const float4* xg = (const float4*)(x + ((size_t)b * NT + (size_t)c * CK) * ND);
        unsigned char* sX = smraw + SM_X;
#pragma unroll
        for (int j = 0; j < 8; ++j) {
            int idx = tid + 256 * j;                 // 2048 float4
            float4 v = xg[idx];
            int token = idx >> 5, k4 = idx & 31;
            int half = k4 >> 4;
            uint32_t off = (uint32_t)(token * 128) +
                           (((uint32_t)(k4 & 15) * 8) ^ ((uint32_t)(token & 7) << 4));
            __nv_bfloat162 h01 = __float22bfloat162_rn(make_float2(v.x, v.y));
            __nv_bfloat162 h23 = __float22bfloat162_rn(make_float2(v.z, v.w));
            __nv_bfloat162 l01 = __float22bfloat162_rn(make_float2(
                v.x - __bfloat162float(h01.x), v.y - __bfloat162float(h01.y)));
            __nv_bfloat162 l23 = __float22bfloat162_rn(make_float2(
                v.z - __bfloat162float(h23.x), v.w - __bfloat162float(h23.y)));
            *(__nv_bfloat162*)(sX + half * 8192 + off)             = h01;
            *(__nv_bfloat162*)(sX + half * 8192 + off + 4)         = h23;
            *(__nv_bfloat162*)(sX + 16384 + half * 8192 + off)     = l01;
            *(__nv_bfloat162*)(sX + 16384 + half * 8192 + off + 4) = l23;
        }
    }
    stage_issue(1, SM_W1);

    // ldmatrix addressing (warp = m-tile rows s0..s0+15, all 64 tokens)
    const int s0 = wid * 16;
    const uint32_t ar = lane & 7, aj = lane >> 3;
    const uint32_t a_rb  = (uint32_t)(s0 + (aj & 1) * 8 + ar) * 128;
    const uint32_t a_k16 = (aj >> 1) * 16;
    const uint32_t a_xor = ar << 4;
    const uint32_t b_row = lane & 7, b_j = lane >> 3;
    const uint32_t b_off = (b_j >> 1) * 1024 + b_row * 128;
    const uint32_t b_k16 = (b_j & 1) * 16;
    const uint32_t b_xor = b_row << 4;

    auto mma_stage = [&](float (*accp)[4], int terms, uint32_t wbuf) {
        for (int tb = 0; tb < terms; ++tb) {
#pragma unroll
            for (int kt = 0; kt < 8; ++kt) {
                const uint32_t half = kt >> 2;
                const uint32_t klo2 = (kt & 3) * 32;
                const uint32_t xb = sbase + SM_X + (uint32_t)tb * 16384 + half * 8192;
                const uint32_t wb = wbuf + half * 16384;
                uint32_t a0[4];
                ldsm_x4(a0, wb + a_rb + ((klo2 + a_k16) ^ a_xor));
#pragma unroll
                for (int i = 0; i < 4; ++i) {
                    uint32_t bfr[4];
                    ldsm_x4(bfr, xb + i * 2048 + b_off + ((klo2 + b_k16) ^ b_xor));
                    mma_bf16(accp[2 * i],     a0, &bfr[0]);
                    mma_bf16(accp[2 * i + 1], a0, &bfr[2]);
                }
            }
        }
    };

    float accDt[8][4], accB[8][4];
#pragma unroll
    for (int nt = 0; nt < 8; ++nt)
#pragma unroll
        for (int q = 0; q < 4; ++q) { accDt[nt][q] = 0.f; accB[nt][q] = 0.f; }

    const uint32_t W0 = sbase + SM_W0, W1 = sbase + SM_W1;
    // stage 0: dt_hi
    CP_WAIT(1); __syncthreads();
    mma_stage(accDt, 2, W0);
    __syncthreads(); stage_issue(2, SM_W0);
    // stage 1: dt_lo
    CP_WAIT(1); __syncthreads();
    mma_stage(accDt, 1, W1);
    __syncthreads(); stage_issue(3, SM_W1);
    // stage 2: B_hi
    CP_WAIT(1); __syncthreads();
    mma_stage(accB, 2, W0);
    __syncthreads(); stage_issue(4, SM_W0);
    // stage 3: B_lo
    CP_WAIT(1); __syncthreads();
    mma_stage(accB, 1, W1);
    __syncthreads(); stage_issue(5, SM_W1);

    // ---- In-register clipped scan (overlaps with C-weight cp.async) ----
    {
        const int dr = lane >> 2, j4 = lane & 3, dc2 = j4 * 2;
        const int sr0 = s0 + dr, sr1 = sr0 + 8;
        const float A0 = -fminf(__expf(__ldg(log_A + sr0)), 10.0f);
        const float A1 = -fminf(__expf(__ldg(log_A + sr1)), 10.0f);
        const float bd0 = __ldg(b_dt + sr0), bd1 = __ldg(b_dt + sr1);
        const size_t pb = (((size_t)b * NC + c) * NS) * (size_t)CK;
        __half* gp0 = g_p  + pb + (size_t)sr0 * CK;
        __half* gp1 = g_p  + pb + (size_t)sr1 * CK;
        __half* gh0 = g_hl + pb + (size_t)sr0 * CK;
        __half* gh1 = g_hl + pb + (size_t)sr1 * CK;
        float cla0 = 0.f, cw0 = 0.f, cla1 = 0.f, cw1 = 0.f;
#pragma unroll
        for (int nt = 0; nt < 8; ++nt) {
            const int t0 = nt * 8 + dc2;
#pragma unroll
            for (int rr = 0; rr < 2; ++rr) {
                const float A_s = rr ? A1 : A0;
                const float bd  = rr ? bd1 : bd0;
                float& cla = rr ? cla1 : cla0;
                float& cw  = rr ? cw1  : cw0;
                float d0 = accDt[nt][rr * 2 + 0] + bd;
                float d1 = accDt[nt][rr * 2 + 1] + bd;
                float sp0 = (d0 > 15.0f) ? d0 : __logf(1.0f + __expf(d0));
                float sp1 = (d1 > 15.0f) ? d1 : __logf(1.0f + __expf(d1));
                float dt0 = fminf(sp0, 1.0f), dt1 = fminf(sp1, 1.0f);
                float la0 = fminf(fmaxf(dt0 * A_s, -0.5f), 0.0f);
                float la1 = fminf(fmaxf(dt1 * A_s, -0.5f), 0.0f);
                float u0 = accB[nt][rr * 2 + 0] * dt0;
                float u1 = accB[nt][rr * 2 + 1] * dt1;
                float xs = quadscan(la0 + la1, j4);
                float cs1 = cla + xs, cs0 = cs1 - la1;
                cla += __shfl_sync(0xFFFFFFFFu, xs, 3, 4);
                float lp0 = fminf(fmaxf(cs0, -30.0f), 0.0f);
                float lp1 = fminf(fmaxf(cs1, -30.0f), 0.0f);
                float p0 = __expf(lp0), p1 = __expf(lp1);
                float w0 = u0 * __expf(-lp0), w1 = u1 * __expf(-lp1);
                float xw = quadscan(w0 + w1, j4);
                float a1v = cw + xw, a0v = a1v - w1;
                cw += __shfl_sync(0xFFFFFFFFu, xw, 3, 4);
                __half2 pp = __floats2half2_rn(p0, p1);
                __half2 hh = __floats2half2_rn(p0 * a0v, p1 * a1v);
                if (rr == 0) { *(__half2*)&gp0[t0] = pp; *(__half2*)&gh0[t0] = hh; }
                else         { *(__half2*)&gp1[t0] = pp; *(__half2*)&gh1[t0] = hh; }
            }
        }
        // compact fp32 tails (all lanes in quad hold full sums; lane j4==0 writes)
        if (j4 == 0) {
            const size_t tb_ = ((size_t)b * NC + c) * NS;
            float tp0 = __expf(fminf(fmaxf(cla0, -30.0f), 0.0f));
            float tp1 = __expf(fminf(fmaxf(cla1, -30.0f), 0.0f));
            g_tp[tb_ + sr0] = tp0;  g_th[tb_ + sr0] = tp0 * cw0;
            g_tp[tb_ + sr1] = tp1;  g_th[tb_ + sr1] = tp1 * cw1;
        }
    }

    // ---- C projection ----
    float accC[8][4];
#pragma unroll
    for (int nt = 0; nt < 8; ++nt)
#pragma unroll
        for (int q = 0; q < 4; ++q) accC[nt][q] = 0.f;

    CP_WAIT(1); __syncthreads();
    mma_stage(accC, 2, W0);
    __syncthreads();
    CP_WAIT(0); __syncthreads();
    mma_stage(accC, 1, W1);

    // store C in [t][s] layout (fp16 scalars)
    {
        const int dr = lane >> 2, dc2 = (lane & 3) * 2;
        const int sr0 = s0 + dr, sr1 = sr0 + 8;
        const size_t gbC = ((size_t)b * NT + (size_t)c * CK) * NS;
#pragma unroll
        for (int nt = 0; nt < 8; ++nt) {
            const int t0 = nt * 8 + dc2;
            g_C[gbC + (size_t)t0 * NS + sr0]       = __float2half(accC[nt][0]);
            g_C[gbC + (size_t)(t0 + 1) * NS + sr0] = __float2half(accC[nt][1]);
            g_C[gbC + (size_t)t0 * NS + sr1]       = __float2half(accC[nt][2]);
            g_C[gbC + (size_t)(t0 + 1) * NS + sr1] = __float2half(accC[nt][3]);
        }
    }
}

// ---------------------------------------------------------------------------
// Pass 2: inter-chunk prefix scan from compact fp32 tails (coalesced)
// ---------------------------------------------------------------------------
#define SMEM2_BYTES (2 * 128 * 128 * 4)

__global__ __launch_bounds__(128)
void pass2_kernel()
{
    extern __shared__ float smf[];
    float* sP = smf;
    float* sH = smf + 128 * 128;
    const int b = blockIdx.x, tid = threadIdx.x;

    const size_t bb = (size_t)b * NC * NS;
    for (int i = tid; i < NC * NS; i += 128) {
        sP[i] = g_tp[bb + i];
        sH[i] = g_th[bb + i];
    }
    __syncthreads();

    const int s = tid;
    float h0 = 0.0f;
    const size_t hb = bb + s;
#pragma unroll 8
    for (int c = 0; c < NC; ++c) {
        g_h0[hb + (size_t)c * NS] = h0;
        h0 = fmaf(sP[c * 128 + s], h0, sH[c * 128 + s]);
    }
}

// ---------------------------------------------------------------------------
// Pass 3 (HMMA, 256 thr, 2 CTAs/SM): C tile prefetched into W region for the
// y-dot (overlaps Loop1); W_hi staged during Loop2; fp16 scratch; bf16 hi/lo
// tiles; 3-term MMA; epilogue overlays W/H regions.
// ---------------------------------------------------------------------------
#define P3_W 0
#define P3_H 32768
#define P3_F 65536
#define P3FS 65
#define P3S  132
#define P3_Y (65536 + 128 * P3FS * 4)
#define SMEM3_BYTES (P3_Y + 1024)

__global__ __launch_bounds__(256, 2)
void pass3_mma(const float* __restrict__ x,
               float* __restrict__ out)
{
    extern __shared__ unsigned char smraw[];
    const uint32_t sbase = smem_u32(smraw);
    float* shf = (float*)(smraw + P3_F);      // [s][65]
    float* sy  = (float*)(smraw + P3_Y);
    float* sh0 = sy + 64;
    float* sx0 = sh0 + 128;
    const int c = blockIdx.x, b = blockIdx.y, tid = threadIdx.x;
    const int wid = tid >> 5, lane = tid & 31;
    const size_t tbase = (size_t)b * NT + (size_t)c * CK;
    const size_t gbase = tbase * NS;

    // Prefetch C tile (16KB fp16, [t][s]) into the W region
    {
        const unsigned char* srcC = (const unsigned char*)(g_C + gbase);
#pragma unroll
        for (int j = 0; j < 4; ++j) {
            int idx = tid + 256 * j;    // 1024 x 16B
            cp_async16(sbase + P3_W + (uint32_t)idx * 16, srcC + (size_t)idx * 16);
        }
        CP_COMMIT();
    }
    if (tid < 128) sh0[tid] = g_h0[((size_t)b * NC + c) * NS + tid];
    else if (tid < 192) sx0[tid - 128] = x[(tbase + tid - 128) * ND];
    __syncthreads();

    // Loop1: h = hl + p*h0 -> shf[s][65]  (coalesced fp16 [s][t] reads,
    // scalar smem stores: stride-65 base is odd for odd s)
    {
        const size_t pb = (((size_t)b * NC + c) * NS) * (size_t)CK;
#pragma unroll
        for (int j = 0; j < 16; ++j) {
            int idx = tid + 256 * j;          // 4096 half2
            int s = idx >> 5, tp = idx & 31;
            int t0 = tp * 2;
            float2 pv = __half22float2(*(const __half2*)&g_p [pb + (size_t)s * CK + t0]);
            float2 hv = __half22float2(*(const __half2*)&g_hl[pb + (size_t)s * CK + t0]);
            float h0s = sh0[s];
            shf[s * P3FS + t0]     = fmaf(pv.x, h0s, hv.x);
            shf[s * P3FS + t0 + 1] = fmaf(pv.y, h0s, hv.y);
        }
    }
    CP_WAIT(0); __syncthreads();

    // y[t] = sum_s C[t][s]*h[s][t]  (C from smem; 8 warps x 8 tokens)
    {
        const __half* sC = (const __half*)(smraw + P3_W);
        for (int t = wid * 8; t < wid * 8 + 8; ++t) {
            float v = 0.0f;
#pragma unroll
            for (int q = 0; q < 2; ++q) {
                int s = 2 * lane + 64 * q;
                float2 cf = __half22float2(*(const __half2*)&sC[t * NS + s]);
                v = fmaf(cf.x, shf[s * P3FS + t], v);
                v = fmaf(cf.y, shf[(s + 1) * P3FS + t], v);
            }
#pragma unroll
            for (int o = 16; o; o >>= 1) v += __shfl_xor_sync(0xFFFFFFFFu, v, o);
            if (lane == 0) sy[t] = v;
        }
    }
    __syncthreads();   // C reads done -> W region reusable

    // Stage W_out_hi (32KB) into W region, overlapping Loop2
    {
#pragma unroll
        for (int j = 0; j < 8; ++j) {
            int idx = tid + 256 * j;
            cp_async16(sbase + P3_W + (uint32_t)idx * 16,
                       g_Wb + (size_t)3 * 65536 + (size_t)idx * 16);
        }
        CP_COMMIT();
    }

    // Loop2: shf -> bf16 hi/lo swizzled tiles (token-row x s-k)
    {
        unsigned char* sH = smraw + P3_H;
#pragma unroll
        for (int j = 0; j < 32; ++j) {
            int idx = tid + 256 * j;          // 8192 elements
            int t = idx >> 7, s = idx & 127;
            float h = shf[s * P3FS + t];
            __nv_bfloat16 hi = __float2bfloat16(h);
            __nv_bfloat16 lo = __float2bfloat16(h - __bfloat162float(hi));
            int half = s >> 6, kl = s & 63;
            uint32_t off = (uint32_t)(t * 128) + (((uint32_t)kl * 2) ^ ((uint32_t)(t & 7) << 4));
            *(__nv_bfloat16*)(sH + half * 8192 + off)         = hi;
            *(__nv_bfloat16*)(sH + 16384 + half * 8192 + off) = lo;
        }
    }
    CP_WAIT(0); __syncthreads();

    // MMA: D[d][t] = W_out h^T, one m16 tile per warp
    const int d0 = wid * 16;
    const uint32_t ar = lane & 7, aj = lane >> 3;
    const uint32_t a_rb  = (uint32_t)(d0 + (aj & 1) * 8 + ar) * 128;
    const uint32_t a_k16 = (aj >> 1) * 16;
    const uint32_t a_xor = ar << 4;
    const uint32_t b_row = lane & 7, b_j = lane >> 3;
    const uint32_t b_off = (b_j >> 1) * 1024 + b_row * 128;
    const uint32_t b_k16 = (b_j & 1) * 16;
    const uint32_t b_xor = b_row << 4;

    float acc[8][4];
#pragma unroll
    for (int nt = 0; nt < 8; ++nt)
#pragma unroll
        for (int q = 0; q < 4; ++q) acc[nt][q] = 0.0f;

    auto run_terms3 = [&](int ntb) {
        for (int tb = 0; tb < ntb; ++tb) {
#pragma unroll
            for (int kt = 0; kt < 8; ++kt) {
                const uint32_t half = kt >> 2;
                const uint32_t klo2 = (kt & 3) * 32;
                const uint32_t xb = sbase + P3_H + (uint32_t)tb * 16384 + half * 8192;
                const uint32_t wb = sbase + P3_W + half * 16384;
                uint32_t a0[4];
                ldsm_x4(a0, wb + a_rb + ((klo2 + a_k16) ^ a_xor));
#pragma unroll
                for (int i = 0; i < 4; ++i) {
                    uint32_t bfr[4];
                    ldsm_x4(bfr, xb + i * 2048 + b_off + ((klo2 + b_k16) ^ b_xor));
                    mma_bf16(acc[2 * i],     a0, &bfr[0]);
                    mma_bf16(acc[2 * i + 1], a0, &bfr[2]);
                }
            }
        }
    };

    run_terms3(2);              // W_hi x (H_hi, H_lo)
    __syncthreads();
    {                            // restage W_lo
#pragma unroll
        for (int j = 0; j < 8; ++j) {
            int idx = tid + 256 * j;
            cp_async16(sbase + P3_W + (uint32_t)idx * 16,
                       g_Wb + (size_t)3 * 65536 + 32768 + (size_t)idx * 16);
        }
        CP_COMMIT();
        CP_WAIT(0);
    }
    __syncthreads();
    run_terms3(1);              // W_lo x H_hi
    __syncthreads();            // W/H reads done -> regions reusable for out

    // fragments -> sOut[t][132] overlaying W/H regions
    {
        float* sOut = (float*)smraw;
        const int dr = lane >> 2, dc = (lane & 3) * 2;
        const int d = d0 + dr;
#pragma unroll
        for (int nt = 0; nt < 8; ++nt) {
            const int t0 = nt * 8 + dc;
            sOut[t0 * P3S + d]           = acc[nt][0];
            sOut[(t0 + 1) * P3S + d]     = acc[nt][1];
            sOut[t0 * P3S + d + 8]       = acc[nt][2];
            sOut[(t0 + 1) * P3S + d + 8] = acc[nt][3];
        }
    }
    __syncthreads();

    // Epilogue: out = staged + y[t]*x[t,0], coalesced float4
    {
        const float* sOut = (const float*)smraw;
        float4* og = (float4*)(out + gbase);
#pragma unroll
        for (int j = 0; j < 8; ++j) {
            int i4 = tid + 256 * j;          // 2048 float4
            int t = i4 >> 5, d4 = i4 & 31;
            float4 v = *(const float4*)&sOut[t * P3S + d4 * 4];
            float yv = sy[t] * sx0[t];
            v.x += yv; v.y += yv; v.z += yv; v.w += yv;
            og[i4] = v;
        }
    }
}

// ---------------------------------------------------------------------------
extern "C" void kernel_launch(void* const* d_in, const int* in_sizes, int n_in,
                              void* d_out, int out_size)
{
    const float* x     = (const float*)d_in[0];
    const float* log_A = (const float*)d_in[1];
    const float* W_B   = (const float*)d_in[2];
    const float* W_C   = (const float*)d_in[3];
    const float* W_dt  = (const float*)d_in[4];
    const float* b_dt  = (const float*)d_in[5];
    const float* W_out = (const float*)d_in[6];
    float* out = (float*)d_out;

    cudaFuncSetAttribute(pass1_mma, cudaFuncAttributeMaxDynamicSharedMemorySize, SMEM1_BYTES);
    cudaFuncSetAttribute(pass2_kernel, cudaFuncAttributeMaxDynamicSharedMemorySize, SMEM2_BYTES);
    cudaFuncSetAttribute(pass3_mma, cudaFuncAttributeMaxDynamicSharedMemorySize, SMEM3_BYTES);

    prep_kernel<<<256, 256>>>(W_B, W_C, W_dt, W_out);
    pass1_mma<<<dim3(NC, NB), 256, SMEM1_BYTES>>>(x, log_A, b_dt);
    pass2_kernel<<<NB, 128, SMEM2_BYTES>>>();
    pass3_mma<<<dim3(NC, NB), 256, SMEM3_BYTES>>>(x, out);
}

// round 16
// speedup vs baseline: 1.3027x; 1.1424x over previous
#include <cuda_runtime.h>
#include <cuda_fp16.h>
#include <cstdint>
#include <cstddef>

#define NB 8
#define NT 8192
#define ND 128
#define NS 128
#define CK 64
#define NC (NT / CK)   // 128

// Scratch (fp16). g_p/g_hl are [b][chunk][s][t] (s-major). g_C is [b][t][s].
__device__ __half g_hl[(size_t)NB * NT * NS];
__device__ __half g_p [(size_t)NB * NT * NS];
__device__ __half g_C [(size_t)NB * NT * NS];
__device__ float  g_h0[(size_t)NB * NC * NS];
__device__ float  g_tp[(size_t)NB * NC * NS];   // chunk tail p   (fp32, compact)
__device__ float  g_th[(size_t)NB * NC * NS];   // chunk tail hl  (fp32, compact)
// Pre-swizzled fp16 hi/lo W tiles: [mat(dt,B,C,out)][term(hi,lo)][khalf] 128r x 64k (16KB)
__device__ __align__(16) unsigned char g_Wb[4 * 2 * 2 * 16384];

__device__ __forceinline__ uint32_t smem_u32(const void* p) {
    uint32_t a;
    asm("{ .reg .u64 t; cvta.to.shared.u64 t, %1; cvt.u32.u64 %0, t; }" : "=r"(a) : "l"(p));
    return a;
}
__device__ __forceinline__ uint32_t sw128(uint32_t off) { return off ^ ((off >> 3) & 0x70); }

__device__ __forceinline__ void cp_async16(uint32_t dst, const void* src) {
    asm volatile("cp.async.cg.shared.global [%0], [%1], 16;" :: "r"(dst), "l"(src));
}
#define CP_COMMIT() asm volatile("cp.async.commit_group;" ::: "memory")
#define CP_WAIT(n)  asm volatile("cp.async.wait_group %0;" :: "n"(n) : "memory")

__device__ __forceinline__ void ldsm_x4(uint32_t* r, uint32_t addr) {
    asm volatile("ldmatrix.sync.aligned.m8n8.x4.shared.b16 {%0,%1,%2,%3}, [%4];"
        : "=r"(r[0]), "=r"(r[1]), "=r"(r[2]), "=r"(r[3]) : "r"(addr));
}
__device__ __forceinline__ void mma_f16(float* d, const uint32_t* a, const uint32_t* b) {
    asm volatile("mma.sync.aligned.m16n8k16.row.col.f32.f16.f16.f32 "
        "{%0,%1,%2,%3}, {%4,%5,%6,%7}, {%8,%9}, {%0,%1,%2,%3};"
        : "+f"(d[0]), "+f"(d[1]), "+f"(d[2]), "+f"(d[3])
        : "r"(a[0]), "r"(a[1]), "r"(a[2]), "r"(a[3]), "r"(b[0]), "r"(b[1]));
}

// Inclusive pair-prefix over the 4-lane quad (width=4 groups = same dr)
__device__ __forceinline__ float quadscan(float v, int j4) {
    float t1 = __shfl_up_sync(0xFFFFFFFFu, v, 1, 4); if (j4 >= 1) v += t1;
    float t2 = __shfl_up_sync(0xFFFFFFFFu, v, 2, 4); if (j4 >= 2) v += t2;
    return v;
}

// ---------------------------------------------------------------------------
// Prep: convert 4 weight mats to swizzled fp16 hi/lo k-half tiles in global.
// ---------------------------------------------------------------------------
__global__ void prep_kernel(const float* __restrict__ W_B,
                            const float* __restrict__ W_C,
                            const float* __restrict__ W_dt,
                            const float* __restrict__ W_out)
{
    int e = blockIdx.x * 256 + threadIdx.x;
    if (e >= 4 * 16384) return;
    int mat = e >> 14, rk = e & 16383, r = rk >> 7, k = rk & 127;
    const float* W = (mat == 0) ? W_dt : (mat == 1) ? W_B : (mat == 2) ? W_C : W_out;
    float w = W[rk];
    __half hi = __float2half(w);
    __half lo = __float2half(w - __half2float(hi));
    int half = k >> 6, kl = k & 63;
    uint32_t off = sw128((uint32_t)(r * 128 + kl * 2));
    *(__half*)&g_Wb[((mat * 2 + 0) * 2 + half) * 16384 + off] = hi;
    *(__half*)&g_Wb[((mat * 2 + 1) * 2 + half) * 16384 + off] = lo;
}

// ---------------------------------------------------------------------------
// Pass 1 (HMMA fp16 2-term, 256 thr, 2 CTAs/SM, 80KB):
// X single fp16 tile (16KB); 6 double-buffered 32KB W stages
// (dt_hi, dt_lo, B_hi, B_lo, C_hi, C_lo), each one MMA pass.
// Scan in fragment registers; fp16 scratch + fp32 compact tails.
// ---------------------------------------------------------------------------
#define SM_X   0
#define SM_W0  16384
#define SM_W1  49152
#define SMEM1_BYTES 81920

__global__ __launch_bounds__(256, 2)
void pass1_mma(const float* __restrict__ x,
               const float* __restrict__ log_A,
               const float* __restrict__ b_dt)
{
    extern __shared__ unsigned char smraw[];
    const uint32_t sbase = smem_u32(smraw);
    const int c = blockIdx.x, b = blockIdx.y, tid = threadIdx.x;
    const int wid = tid >> 5, lane = tid & 31;

    auto stage_issue = [&](int sid, uint32_t dstoff) {
        const unsigned char* src = g_Wb + (size_t)sid * 32768;
#pragma unroll
        for (int j = 0; j < 8; ++j) {
            int idx = tid + 256 * j;     // 2048 x 16B = 32KB
            cp_async16(sbase + dstoff + (uint32_t)idx * 16, src + (size_t)idx * 16);
        }
        CP_COMMIT();
    };

    stage_issue(0, SM_W0);

    // Convert X chunk (64 tok x 128) to a single fp16 swizzled tile (16KB)
    {
        const float4* xg = (const float4*)(x + ((size_t)b * NT + (size_t)c * CK) * ND);
        unsigned char* sX = smraw + SM_X;
#pragma unroll
        for (int j = 0; j < 8; ++j) {
            int idx = tid + 256 * j;                 // 2048 float4
            float4 v = xg[idx];
            int token = idx >> 5, k4 = idx & 31;
            int half = k4 >> 4;
            uint32_t off = (uint32_t)(token * 128) +
                           (((uint32_t)(k4 & 15) * 8) ^ ((uint32_t)(token & 7) << 4));
            *(__half2*)(sX + half * 8192 + off)     = __floats2half2_rn(v.x, v.y);
            *(__half2*)(sX + half * 8192 + off + 4) = __floats2half2_rn(v.z, v.w);
        }
    }
    stage_issue(1, SM_W1);

    // ldmatrix addressing (warp = m-tile rows s0..s0+15, all 64 tokens)
    const int s0 = wid * 16;
    const uint32_t ar = lane & 7, aj = lane >> 3;
    const uint32_t a_rb  = (uint32_t)(s0 + (aj & 1) * 8 + ar) * 128;
    const uint32_t a_k16 = (aj >> 1) * 16;
    const uint32_t a_xor = ar << 4;
    const uint32_t b_row = lane & 7, b_j = lane >> 3;
    const uint32_t b_off = (b_j >> 1) * 1024 + b_row * 128;
    const uint32_t b_k16 = (b_j & 1) * 16;
    const uint32_t b_xor = b_row << 4;

    auto mma_pass = [&](float (*accp)[4], uint32_t wbuf) {
#pragma unroll
        for (int kt = 0; kt < 8; ++kt) {
            const uint32_t half = kt >> 2;
            const uint32_t klo2 = (kt & 3) * 32;
            const uint32_t xb = sbase + SM_X + half * 8192;
            const uint32_t wb = wbuf + half * 16384;
            uint32_t a0[4];
            ldsm_x4(a0, wb + a_rb + ((klo2 + a_k16) ^ a_xor));
#pragma unroll
            for (int i = 0; i < 4; ++i) {
                uint32_t bfr[4];
                ldsm_x4(bfr, xb + i * 2048 + b_off + ((klo2 + b_k16) ^ b_xor));
                mma_f16(accp[2 * i],     a0, &bfr[0]);
                mma_f16(accp[2 * i + 1], a0, &bfr[2]);
            }
        }
    };

    float accDt[8][4], accB[8][4];
#pragma unroll
    for (int nt = 0; nt < 8; ++nt)
#pragma unroll
        for (int q = 0; q < 4; ++q) { accDt[nt][q] = 0.f; accB[nt][q] = 0.f; }

    const uint32_t W0 = sbase + SM_W0, W1 = sbase + SM_W1;
    // dt_hi
    CP_WAIT(1); __syncthreads();
    mma_pass(accDt, W0);
    __syncthreads(); stage_issue(2, SM_W0);   // B_hi
    // dt_lo
    CP_WAIT(1); __syncthreads();
    mma_pass(accDt, W1);
    __syncthreads(); stage_issue(3, SM_W1);   // B_lo
    // B_hi
    CP_WAIT(1); __syncthreads();
    mma_pass(accB, W0);
    __syncthreads(); stage_issue(4, SM_W0);   // C_hi
    // B_lo
    CP_WAIT(1); __syncthreads();
    mma_pass(accB, W1);
    __syncthreads(); stage_issue(5, SM_W1);   // C_lo

    // ---- In-register clipped scan (overlaps with C-weight cp.async) ----
    {
        const int dr = lane >> 2, j4 = lane & 3, dc2 = j4 * 2;
        const int sr0 = s0 + dr, sr1 = sr0 + 8;
        const float A0 = -fminf(__expf(__ldg(log_A + sr0)), 10.0f);
        const float A1 = -fminf(__expf(__ldg(log_A + sr1)), 10.0f);
        const float bd0 = __ldg(b_dt + sr0), bd1 = __ldg(b_dt + sr1);
        const size_t pb = (((size_t)b * NC + c) * NS) * (size_t)CK;
        __half* gp0 = g_p  + pb + (size_t)sr0 * CK;
        __half* gp1 = g_p  + pb + (size_t)sr1 * CK;
        __half* gh0 = g_hl + pb + (size_t)sr0 * CK;
        __half* gh1 = g_hl + pb + (size_t)sr1 * CK;
        float cla0 = 0.f, cw0 = 0.f, cla1 = 0.f, cw1 = 0.f;
#pragma unroll
        for (int nt = 0; nt < 8; ++nt) {
            const int t0 = nt * 8 + dc2;
#pragma unroll
            for (int rr = 0; rr < 2; ++rr) {
                const float A_s = rr ? A1 : A0;
                const float bd  = rr ? bd1 : bd0;
                float& cla = rr ? cla1 : cla0;
                float& cw  = rr ? cw1  : cw0;
                float d0 = accDt[nt][rr * 2 + 0] + bd;
                float d1 = accDt[nt][rr * 2 + 1] + bd;
                float sp0 = (d0 > 15.0f) ? d0 : __logf(1.0f + __expf(d0));
                float sp1 = (d1 > 15.0f) ? d1 : __logf(1.0f + __expf(d1));
                float dt0 = fminf(sp0, 1.0f), dt1 = fminf(sp1, 1.0f);
                float la0 = fminf(fmaxf(dt0 * A_s, -0.5f), 0.0f);
                float la1 = fminf(fmaxf(dt1 * A_s, -0.5f), 0.0f);
                float u0 = accB[nt][rr * 2 + 0] * dt0;
                float u1 = accB[nt][rr * 2 + 1] * dt1;
                float xs = quadscan(la0 + la1, j4);
                float cs1 = cla + xs, cs0 = cs1 - la1;
                cla += __shfl_sync(0xFFFFFFFFu, xs, 3, 4);
                float lp0 = fminf(fmaxf(cs0, -30.0f), 0.0f);
                float lp1 = fminf(fmaxf(cs1, -30.0f), 0.0f);
                float p0 = __expf(lp0), p1 = __expf(lp1);
                float w0 = u0 * __expf(-lp0), w1 = u1 * __expf(-lp1);
                float xw = quadscan(w0 + w1, j4);
                float a1v = cw + xw, a0v = a1v - w1;
                cw += __shfl_sync(0xFFFFFFFFu, xw, 3, 4);
                __half2 pp = __floats2half2_rn(p0, p1);
                __half2 hh = __floats2half2_rn(p0 * a0v, p1 * a1v);
                if (rr == 0) { *(__half2*)&gp0[t0] = pp; *(__half2*)&gh0[t0] = hh; }
                else         { *(__half2*)&gp1[t0] = pp; *(__half2*)&gh1[t0] = hh; }
            }
        }
        // compact fp32 tails
        if (j4 == 0) {
            const size_t tb_ = ((size_t)b * NC + c) * NS;
            float tp0 = __expf(fminf(fmaxf(cla0, -30.0f), 0.0f));
            float tp1 = __expf(fminf(fmaxf(cla1, -30.0f), 0.0f));
            g_tp[tb_ + sr0] = tp0;  g_th[tb_ + sr0] = tp0 * cw0;
            g_tp[tb_ + sr1] = tp1;  g_th[tb_ + sr1] = tp1 * cw1;
        }
    }

    // ---- C projection ----
    float accC[8][4];
#pragma unroll
    for (int nt = 0; nt < 8; ++nt)
#pragma unroll
        for (int q = 0; q < 4; ++q) accC[nt][q] = 0.f;

    CP_WAIT(1); __syncthreads();
    mma_pass(accC, W0);
    __syncthreads();
    CP_WAIT(0); __syncthreads();
    mma_pass(accC, W1);

    // store C in [t][s] layout (fp16 scalars)
    {
        const int dr = lane >> 2, dc2 = (lane & 3) * 2;
        const int sr0 = s0 + dr, sr1 = sr0 + 8;
        const size_t gbC = ((size_t)b * NT + (size_t)c * CK) * NS;
#pragma unroll
        for (int nt = 0; nt < 8; ++nt) {
            const int t0 = nt * 8 + dc2;
            g_C[gbC + (size_t)t0 * NS + sr0]       = __float2half(accC[nt][0]);
            g_C[gbC + (size_t)(t0 + 1) * NS + sr0] = __float2half(accC[nt][1]);
            g_C[gbC + (size_t)t0 * NS + sr1]       = __float2half(accC[nt][2]);
            g_C[gbC + (size_t)(t0 + 1) * NS + sr1] = __float2half(accC[nt][3]);
        }
    }
}

// ---------------------------------------------------------------------------
// Pass 2: inter-chunk prefix scan from compact fp32 tails (coalesced)
// ---------------------------------------------------------------------------
#define SMEM2_BYTES (2 * 128 * 128 * 4)

__global__ __launch_bounds__(128)
void pass2_kernel()
{
    extern __shared__ float smf[];
    float* sP = smf;
    float* sH = smf + 128 * 128;
    const int b = blockIdx.x, tid = threadIdx.x;

    const size_t bb = (size_t)b * NC * NS;
    for (int i = tid; i < NC * NS; i += 128) {
        sP[i] = g_tp[bb + i];
        sH[i] = g_th[bb + i];
    }
    __syncthreads();

    const int s = tid;
    float h0 = 0.0f;
    const size_t hb = bb + s;
#pragma unroll 8
    for (int c = 0; c < NC; ++c) {
        g_h0[hb + (size_t)c * NS] = h0;
        h0 = fmaf(sP[c * 128 + s], h0, sH[c * 128 + s]);
    }
}

// ---------------------------------------------------------------------------
// Pass 3 (HMMA fp16 2-term, 256 thr, 2 CTAs/SM, ~82KB):
// C tile prefetched into W region for the y-dot (overlaps Loop1);
// H single fp16 tile (16KB); W_out hi then lo staged; epilogue overlays W/H.
// ---------------------------------------------------------------------------
#define P3_W 0
#define P3_H 32768
#define P3_F 49152
#define P3FS 65
#define P3S  132
#define P3_Y (49152 + 128 * P3FS * 4)
#define SMEM3_BYTES (P3_Y + 1024)

__global__ __launch_bounds__(256, 2)
void pass3_mma(const float* __restrict__ x,
               float* __restrict__ out)
{
    extern __shared__ unsigned char smraw[];
    const uint32_t sbase = smem_u32(smraw);
    float* shf = (float*)(smraw + P3_F);      // [s][65]
    float* sy  = (float*)(smraw + P3_Y);
    float* sh0 = sy + 64;
    float* sx0 = sh0 + 128;
    const int c = blockIdx.x, b = blockIdx.y, tid = threadIdx.x;
    const int wid = tid >> 5, lane = tid & 31;
    const size_t tbase = (size_t)b * NT + (size_t)c * CK;
    const size_t gbase = tbase * NS;

    // Prefetch C tile (16KB fp16, [t][s]) into the W region
    {
        const unsigned char* srcC = (const unsigned char*)(g_C + gbase);
#pragma unroll
        for (int j = 0; j < 4; ++j) {
            int idx = tid + 256 * j;    // 1024 x 16B
            cp_async16(sbase + P3_W + (uint32_t)idx * 16, srcC + (size_t)idx * 16);
        }
        CP_COMMIT();
    }
    if (tid < 128) sh0[tid] = g_h0[((size_t)b * NC + c) * NS + tid];
    else if (tid < 192) sx0[tid - 128] = x[(tbase + tid - 128) * ND];
    __syncthreads();

    // Loop1: h = hl + p*h0 -> shf[s][65]
    {
        const size_t pb = (((size_t)b * NC + c) * NS) * (size_t)CK;
#pragma unroll
        for (int j = 0; j < 16; ++j) {
            int idx = tid + 256 * j;          // 4096 half2
            int s = idx >> 5, tp = idx & 31;
            int t0 = tp * 2;
            float2 pv = __half22float2(*(const __half2*)&g_p [pb + (size_t)s * CK + t0]);
            float2 hv = __half22float2(*(const __half2*)&g_hl[pb + (size_t)s * CK + t0]);
            float h0s = sh0[s];
            shf[s * P3FS + t0]     = fmaf(pv.x, h0s, hv.x);
            shf[s * P3FS + t0 + 1] = fmaf(pv.y, h0s, hv.y);
        }
    }
    CP_WAIT(0); __syncthreads();

    // y[t] = sum_s C[t][s]*h[s][t]  (C from smem; 8 warps x 8 tokens)
    {
        const __half* sC = (const __half*)(smraw + P3_W);
        for (int t = wid * 8; t < wid * 8 + 8; ++t) {
            float v = 0.0f;
#pragma unroll
            for (int q = 0; q < 2; ++q) {
                int s = 2 * lane + 64 * q;
                float2 cf = __half22float2(*(const __half2*)&sC[t * NS + s]);
                v = fmaf(cf.x, shf[s * P3FS + t], v);
                v = fmaf(cf.y, shf[(s + 1) * P3FS + t], v);
            }
#pragma unroll
            for (int o = 16; o; o >>= 1) v += __shfl_xor_sync(0xFFFFFFFFu, v, o);
            if (lane == 0) sy[t] = v;
        }
    }
    __syncthreads();   // C reads done -> W region reusable

    // Stage W_out_hi (32KB) into W region, overlapping Loop2
    {
#pragma unroll
        for (int j = 0; j < 8; ++j) {
            int idx = tid + 256 * j;
            cp_async16(sbase + P3_W + (uint32_t)idx * 16,
                       g_Wb + (size_t)3 * 65536 + (size_t)idx * 16);
        }
        CP_COMMIT();
    }

    // Loop2: shf -> single fp16 swizzled tile (token-row x s-k)
    {
        unsigned char* sH = smraw + P3_H;
#pragma unroll
        for (int j = 0; j < 32; ++j) {
            int idx = tid + 256 * j;          // 8192 elements
            int t = idx >> 7, s = idx & 127;
            float h = shf[s * P3FS + t];
            int half = s >> 6, kl = s & 63;
            uint32_t off = (uint32_t)(t * 128) + (((uint32_t)kl * 2) ^ ((uint32_t)(t & 7) << 4));
            *(__half*)(sH + half * 8192 + off) = __float2half(h);
        }
    }
    CP_WAIT(0); __syncthreads();

    // MMA: D[d][t] = W_out h^T, one m16 tile per warp, 2 fp16 terms
    const int d0 = wid * 16;
    const uint32_t ar = lane & 7, aj = lane >> 3;
    const uint32_t a_rb  = (uint32_t)(d0 + (aj & 1) * 8 + ar) * 128;
    const uint32_t a_k16 = (aj >> 1) * 16;
    const uint32_t a_xor = ar << 4;
    const uint32_t b_row = lane & 7, b_j = lane >> 3;
    const uint32_t b_off = (b_j >> 1) * 1024 + b_row * 128;
    const uint32_t b_k16 = (b_j & 1) * 16;
    const uint32_t b_xor = b_row << 4;

    float acc[8][4];
#pragma unroll
    for (int nt = 0; nt < 8; ++nt)
#pragma unroll
        for (int q = 0; q < 4; ++q) acc[nt][q] = 0.0f;

    auto mma_pass3 = [&]() {
#pragma unroll
        for (int kt = 0; kt < 8; ++kt) {
            const uint32_t half = kt >> 2;
            const uint32_t klo2 = (kt & 3) * 32;
            const uint32_t xb = sbase + P3_H + half * 8192;
            const uint32_t wb = sbase + P3_W + half * 16384;
            uint32_t a0[4];
            ldsm_x4(a0, wb + a_rb + ((klo2 + a_k16) ^ a_xor));
#pragma unroll
            for (int i = 0; i < 4; ++i) {
                uint32_t bfr[4];
                ldsm_x4(bfr, xb + i * 2048 + b_off + ((klo2 + b_k16) ^ b_xor));
                mma_f16(acc[2 * i],     a0, &bfr[0]);
                mma_f16(acc[2 * i + 1], a0, &bfr[2]);
            }
        }
    };

    mma_pass3();                 // W_hi x H
    __syncthreads();
    {                            // restage W_lo
#pragma unroll
        for (int j = 0; j < 8; ++j) {
            int idx = tid + 256 * j;
            cp_async16(sbase + P3_W + (uint32_t)idx * 16,
                       g_Wb + (size_t)3 * 65536 + 32768 + (size_t)idx * 16);
        }
        CP_COMMIT();
        CP_WAIT(0);
    }
    __syncthreads();
    mma_pass3();                 // W_lo x H
    __syncthreads();             // W/H reads done -> regions reusable for out

    // fragments -> sOut[t][132] overlaying W/H regions
    {
        float* sOut = (float*)smraw;
        const int dr = lane >> 2, dc = (lane & 3) * 2;
        const int d = d0 + dr;
#pragma unroll
        for (int nt = 0; nt < 8; ++nt) {
            const int t0 = nt * 8 + dc;
            sOut[t0 * P3S + d]           = acc[nt][0];
            sOut[(t0 + 1) * P3S + d]     = acc[nt][1];
            sOut[t0 * P3S + d + 8]       = acc[nt][2];
            sOut[(t0 + 1) * P3S + d + 8] = acc[nt][3];
        }
    }
    __syncthreads();

    // Epilogue: out = staged + y[t]*x[t,0], coalesced float4
    {
        const float* sOut = (const float*)smraw;
        float4* og = (float4*)(out + gbase);
#pragma unroll
        for (int j = 0; j < 8; ++j) {
            int i4 = tid + 256 * j;          // 2048 float4
            int t = i4 >> 5, d4 = i4 & 31;
            float4 v = *(const float4*)&sOut[t * P3S + d4 * 4];
            float yv = sy[t] * sx0[t];
            v.x += yv; v.y += yv; v.z += yv; v.w += yv;
            og[i4] = v;
        }
    }
}

// ---------------------------------------------------------------------------
extern "C" void kernel_launch(void* const* d_in, const int* in_sizes, int n_in,
                              void* d_out, int out_size)
{
    const float* x     = (const float*)d_in[0];
    const float* log_A = (const float*)d_in[1];
    const float* W_B   = (const float*)d_in[2];
    const float* W_C   = (const float*)d_in[3];
    const float* W_dt  = (const float*)d_in[4];
    const float* b_dt  = (const float*)d_in[5];
    const float* W_out = (const float*)d_in[6];
    float* out = (float*)d_out;

    cudaFuncSetAttribute(pass1_mma, cudaFuncAttributeMaxDynamicSharedMemorySize, SMEM1_BYTES);
    cudaFuncSetAttribute(pass2_kernel, cudaFuncAttributeMaxDynamicSharedMemorySize, SMEM2_BYTES);
    cudaFuncSetAttribute(pass3_mma, cudaFuncAttributeMaxDynamicSharedMemorySize, SMEM3_BYTES);

    prep_kernel<<<256, 256>>>(W_B, W_C, W_dt, W_out);
    pass1_mma<<<dim3(NC, NB), 256, SMEM1_BYTES>>>(x, log_A, b_dt);
    pass2_kernel<<<NB, 128, SMEM2_BYTES>>>();
    pass3_mma<<<dim3(NC, NB), 256, SMEM3_BYTES>>>(x, out);
}

// round 17
// speedup vs baseline: 1.4032x; 1.0772x over previous
#include <cuda_runtime.h>
#include <cuda_fp16.h>
#include <cstdint>
#include <cstddef>

#define NB 8
#define NT 8192
#define ND 128
#define NS 128
#define CK 64
#define NC (NT / CK)   // 128

// Scratch (fp16). g_p/g_hl are [b][chunk][s][t] (s-major). g_C is [b][t][s].
__device__ __half g_hl[(size_t)NB * NT * NS];
__device__ __half g_p [(size_t)NB * NT * NS];
__device__ __half g_C [(size_t)NB * NT * NS];
__device__ float  g_h0[(size_t)NB * NC * NS];
__device__ float  g_tp[(size_t)NB * NC * NS];   // chunk tail p   (fp32, compact)
__device__ float  g_th[(size_t)NB * NC * NS];   // chunk tail hl  (fp32, compact)
// Pre-swizzled fp16 hi/lo W tiles: [mat(dt,B,C,out)][term(hi,lo)][khalf] 128r x 64k (16KB)
__device__ __align__(16) unsigned char g_Wb[4 * 2 * 2 * 16384];

__device__ __forceinline__ uint32_t smem_u32(const void* p) {
    uint32_t a;
    asm("{ .reg .u64 t; cvta.to.shared.u64 t, %1; cvt.u32.u64 %0, t; }" : "=r"(a) : "l"(p));
    return a;
}
__device__ __forceinline__ uint32_t sw128(uint32_t off) { return off ^ ((off >> 3) & 0x70); }

__device__ __forceinline__ void cp_async16(uint32_t dst, const void* src) {
    asm volatile("cp.async.cg.shared.global [%0], [%1], 16;" :: "r"(dst), "l"(src));
}
#define CP_COMMIT() asm volatile("cp.async.commit_group;" ::: "memory")
#define CP_WAIT(n)  asm volatile("cp.async.wait_group %0;" :: "n"(n) : "memory")

__device__ __forceinline__ void ldsm_x4(uint32_t* r, uint32_t addr) {
    asm volatile("ldmatrix.sync.aligned.m8n8.x4.shared.b16 {%0,%1,%2,%3}, [%4];"
        : "=r"(r[0]), "=r"(r[1]), "=r"(r[2]), "=r"(r[3]) : "r"(addr));
}
__device__ __forceinline__ void mma_f16(float* d, const uint32_t* a, const uint32_t* b) {
    asm volatile("mma.sync.aligned.m16n8k16.row.col.f32.f16.f16.f32 "
        "{%0,%1,%2,%3}, {%4,%5,%6,%7}, {%8,%9}, {%0,%1,%2,%3};"
        : "+f"(d[0]), "+f"(d[1]), "+f"(d[2]), "+f"(d[3])
        : "r"(a[0]), "r"(a[1]), "r"(a[2]), "r"(a[3]), "r"(b[0]), "r"(b[1]));
}

// Inclusive pair-prefix over the 4-lane quad (width=4 groups = same dr)
__device__ __forceinline__ float quadscan(float v, int j4) {
    float t1 = __shfl_up_sync(0xFFFFFFFFu, v, 1, 4); if (j4 >= 1) v += t1;
    float t2 = __shfl_up_sync(0xFFFFFFFFu, v, 2, 4); if (j4 >= 2) v += t2;
    return v;
}

// ---------------------------------------------------------------------------
// Prep: convert 4 weight mats to swizzled fp16 hi/lo k-half tiles in global.
// ---------------------------------------------------------------------------
__global__ void prep_kernel(const float* __restrict__ W_B,
                            const float* __restrict__ W_C,
                            const float* __restrict__ W_dt,
                            const float* __restrict__ W_out)
{
    int e = blockIdx.x * 256 + threadIdx.x;
    if (e >= 4 * 16384) return;
    int mat = e >> 14, rk = e & 16383, r = rk >> 7, k = rk & 127;
    const float* W = (mat == 0) ? W_dt : (mat == 1) ? W_B : (mat == 2) ? W_C : W_out;
    float w = W[rk];
    __half hi = __float2half(w);
    __half lo = __float2half(w - __half2float(hi));
    int half = k >> 6, kl = k & 63;
    uint32_t off = sw128((uint32_t)(r * 128 + kl * 2));
    *(__half*)&g_Wb[((mat * 2 + 0) * 2 + half) * 16384 + off] = hi;
    *(__half*)&g_Wb[((mat * 2 + 1) * 2 + half) * 16384 + off] = lo;
}

// ---------------------------------------------------------------------------
// Pass 1 (HMMA fp16 paired-term, 256 thr, 2 CTAs/SM, 112KB):
// X 16KB + 3x32KB W buffers. Per mat ONE paired MMA pass (hi+lo share B frags).
// Pipeline: (dt_hi,dt_lo)+B_hi staged over X convert; B_lo over dt pass;
// (C_hi,C_lo) over the scan. Fragment-register scan; fp16 scratch; fp32 tails.
// ---------------------------------------------------------------------------
#define SM_X   0
#define SM_WA  16384
#define SM_WB  49152
#define SM_WC  81920
#define SMEM1_BYTES 114688

__global__ __launch_bounds__(256, 2)
void pass1_mma(const float* __restrict__ x,
               const float* __restrict__ log_A,
               const float* __restrict__ b_dt)
{
    extern __shared__ unsigned char smraw[];
    const uint32_t sbase = smem_u32(smraw);
    const int c = blockIdx.x, b = blockIdx.y, tid = threadIdx.x;
    const int wid = tid >> 5, lane = tid & 31;

    auto stage_tile = [&](int sid, uint32_t dstoff) {   // 32KB, no commit
        const unsigned char* src = g_Wb + (size_t)sid * 32768;
#pragma unroll
        for (int j = 0; j < 8; ++j) {
            int idx = tid + 256 * j;
            cp_async16(sbase + dstoff + (uint32_t)idx * 16, src + (size_t)idx * 16);
        }
    };

    stage_tile(0, SM_WA); stage_tile(1, SM_WB); CP_COMMIT();   // G1: dt_hi + dt_lo
    stage_tile(2, SM_WC); CP_COMMIT();                          // G2: B_hi

    // Convert X chunk (64 tok x 128) to a single fp16 swizzled tile (16KB)
    {
        const float4* xg = (const float4*)(x + ((size_t)b * NT + (size_t)c * CK) * ND);
        unsigned char* sX = smraw + SM_X;
#pragma unroll
        for (int j = 0; j < 8; ++j) {
            int idx = tid + 256 * j;                 // 2048 float4
            float4 v = xg[idx];
            int token = idx >> 5, k4 = idx & 31;
            int half = k4 >> 4;
            uint32_t off = (uint32_t)(token * 128) +
                           (((uint32_t)(k4 & 15) * 8) ^ ((uint32_t)(token & 7) << 4));
            *(__half2*)(sX + half * 8192 + off)     = __floats2half2_rn(v.x, v.y);
            *(__half2*)(sX + half * 8192 + off + 4) = __floats2half2_rn(v.z, v.w);
        }
    }

    // ldmatrix addressing (warp = m-tile rows s0..s0+15, all 64 tokens)
    const int s0 = wid * 16;
    const uint32_t ar = lane & 7, aj = lane >> 3;
    const uint32_t a_rb  = (uint32_t)(s0 + (aj & 1) * 8 + ar) * 128;
    const uint32_t a_k16 = (aj >> 1) * 16;
    const uint32_t a_xor = ar << 4;
    const uint32_t b_row = lane & 7, b_j = lane >> 3;
    const uint32_t b_off = (b_j >> 1) * 1024 + b_row * 128;
    const uint32_t b_k16 = (b_j & 1) * 16;
    const uint32_t b_xor = b_row << 4;

    // Paired-term MMA pass: acc += W_hi*X + W_lo*X, B frags loaded once
    auto mma_pair = [&](float (*accp)[4], uint32_t w0off, uint32_t w1off) {
#pragma unroll
        for (int kt = 0; kt < 8; ++kt) {
            const uint32_t half = kt >> 2;
            const uint32_t klo2 = (kt & 3) * 32;
            const uint32_t xb = sbase + SM_X + half * 8192;
            const uint32_t wa = half * 16384 + a_rb + ((klo2 + a_k16) ^ a_xor);
            uint32_t a0[4], a1[4];
            ldsm_x4(a0, sbase + w0off + wa);
            ldsm_x4(a1, sbase + w1off + wa);
#pragma unroll
            for (int i = 0; i < 4; ++i) {
                uint32_t bfr[4];
                ldsm_x4(bfr, xb + i * 2048 + b_off + ((klo2 + b_k16) ^ b_xor));
                mma_f16(accp[2 * i],     a0, &bfr[0]);
                mma_f16(accp[2 * i + 1], a0, &bfr[2]);
                mma_f16(accp[2 * i],     a1, &bfr[0]);
                mma_f16(accp[2 * i + 1], a1, &bfr[2]);
            }
        }
    };

    float accDt[8][4], accB[8][4];
#pragma unroll
    for (int nt = 0; nt < 8; ++nt)
#pragma unroll
        for (int q = 0; q < 4; ++q) { accDt[nt][q] = 0.f; accB[nt][q] = 0.f; }

    // dt pass (W_A=dt_hi, W_B=dt_lo)
    CP_WAIT(1); __syncthreads();
    mma_pair(accDt, SM_WA, SM_WB);
    __syncthreads();
    stage_tile(3, SM_WA); CP_COMMIT();        // G3: B_lo -> WA
    // B pass (W_C=B_hi, W_A=B_lo)
    CP_WAIT(0); __syncthreads();
    mma_pair(accB, SM_WC, SM_WA);
    __syncthreads();
    stage_tile(4, SM_WB); stage_tile(5, SM_WC); CP_COMMIT();   // G4: C_hi+C_lo

    // ---- In-register clipped scan (overlaps with C staging) ----
    {
        const int dr = lane >> 2, j4 = lane & 3, dc2 = j4 * 2;
        const int sr0 = s0 + dr, sr1 = sr0 + 8;
        const float A0 = -fminf(__expf(__ldg(log_A + sr0)), 10.0f);
        const float A1 = -fminf(__expf(__ldg(log_A + sr1)), 10.0f);
        const float bd0 = __ldg(b_dt + sr0), bd1 = __ldg(b_dt + sr1);
        const size_t pb = (((size_t)b * NC + c) * NS) * (size_t)CK;
        __half* gp0 = g_p  + pb + (size_t)sr0 * CK;
        __half* gp1 = g_p  + pb + (size_t)sr1 * CK;
        __half* gh0 = g_hl + pb + (size_t)sr0 * CK;
        __half* gh1 = g_hl + pb + (size_t)sr1 * CK;
        float cla0 = 0.f, cw0 = 0.f, cla1 = 0.f, cw1 = 0.f;
#pragma unroll
        for (int nt = 0; nt < 8; ++nt) {
            const int t0 = nt * 8 + dc2;
#pragma unroll
            for (int rr = 0; rr < 2; ++rr) {
                const float A_s = rr ? A1 : A0;
                const float bd  = rr ? bd1 : bd0;
                float& cla = rr ? cla1 : cla0;
                float& cw  = rr ? cw1  : cw0;
                float d0 = accDt[nt][rr * 2 + 0] + bd;
                float d1 = accDt[nt][rr * 2 + 1] + bd;
                float sp0 = (d0 > 15.0f) ? d0 : __logf(1.0f + __expf(d0));
                float sp1 = (d1 > 15.0f) ? d1 : __logf(1.0f + __expf(d1));
                float dt0 = fminf(sp0, 1.0f), dt1 = fminf(sp1, 1.0f);
                float la0 = fminf(fmaxf(dt0 * A_s, -0.5f), 0.0f);
                float la1 = fminf(fmaxf(dt1 * A_s, -0.5f), 0.0f);
                float u0 = accB[nt][rr * 2 + 0] * dt0;
                float u1 = accB[nt][rr * 2 + 1] * dt1;
                float xs = quadscan(la0 + la1, j4);
                float cs1 = cla + xs, cs0 = cs1 - la1;
                cla += __shfl_sync(0xFFFFFFFFu, xs, 3, 4);
                float lp0 = fminf(fmaxf(cs0, -30.0f), 0.0f);
                float lp1 = fminf(fmaxf(cs1, -30.0f), 0.0f);
                float p0 = __expf(lp0), p1 = __expf(lp1);
                float w0 = u0 * __expf(-lp0), w1 = u1 * __expf(-lp1);
                float xw = quadscan(w0 + w1, j4);
                float a1v = cw + xw, a0v = a1v - w1;
                cw += __shfl_sync(0xFFFFFFFFu, xw, 3, 4);
                __half2 pp = __floats2half2_rn(p0, p1);
                __half2 hh = __floats2half2_rn(p0 * a0v, p1 * a1v);
                if (rr == 0) { *(__half2*)&gp0[t0] = pp; *(__half2*)&gh0[t0] = hh; }
                else         { *(__half2*)&gp1[t0] = pp; *(__half2*)&gh1[t0] = hh; }
            }
        }
        if (j4 == 0) {
            const size_t tb_ = ((size_t)b * NC + c) * NS;
            float tp0 = __expf(fminf(fmaxf(cla0, -30.0f), 0.0f));
            float tp1 = __expf(fminf(fmaxf(cla1, -30.0f), 0.0f));
            g_tp[tb_ + sr0] = tp0;  g_th[tb_ + sr0] = tp0 * cw0;
            g_tp[tb_ + sr1] = tp1;  g_th[tb_ + sr1] = tp1 * cw1;
        }
    }

    // ---- C projection (paired) ----
    float accC[8][4];
#pragma unroll
    for (int nt = 0; nt < 8; ++nt)
#pragma unroll
        for (int q = 0; q < 4; ++q) accC[nt][q] = 0.f;

    CP_WAIT(0); __syncthreads();
    mma_pair(accC, SM_WB, SM_WC);

    // store C in [t][s] layout (fp16 scalars)
    {
        const int dr = lane >> 2, dc2 = (lane & 3) * 2;
        const int sr0 = s0 + dr, sr1 = sr0 + 8;
        const size_t gbC = ((size_t)b * NT + (size_t)c * CK) * NS;
#pragma unroll
        for (int nt = 0; nt < 8; ++nt) {
            const int t0 = nt * 8 + dc2;
            g_C[gbC + (size_t)t0 * NS + sr0]       = __float2half(accC[nt][0]);
            g_C[gbC + (size_t)(t0 + 1) * NS + sr0] = __float2half(accC[nt][1]);
            g_C[gbC + (size_t)t0 * NS + sr1]       = __float2half(accC[nt][2]);
            g_C[gbC + (size_t)(t0 + 1) * NS + sr1] = __float2half(accC[nt][3]);
        }
    }
}

// ---------------------------------------------------------------------------
// Pass 2: inter-chunk prefix scan from compact fp32 tails (coalesced)
// ---------------------------------------------------------------------------
#define SMEM2_BYTES (2 * 128 * 128 * 4)

__global__ __launch_bounds__(128)
void pass2_kernel()
{
    extern __shared__ float smf[];
    float* sP = smf;
    float* sH = smf + 128 * 128;
    const int b = blockIdx.x, tid = threadIdx.x;

    const size_t bb = (size_t)b * NC * NS;
    for (int i = tid; i < NC * NS; i += 128) {
        sP[i] = g_tp[bb + i];
        sH[i] = g_th[bb + i];
    }
    __syncthreads();

    const int s = tid;
    float h0 = 0.0f;
    const size_t hb = bb + s;
#pragma unroll 8
    for (int c = 0; c < NC; ++c) {
        g_h0[hb + (size_t)c * NS] = h0;
        h0 = fmaf(sP[c * 128 + s], h0, sH[c * 128 + s]);
    }
}

// ---------------------------------------------------------------------------
// Pass 3 (HMMA fp16 paired-term, 256 thr, 2 CTAs/SM, ~98KB):
// W_hi+W_lo staged ONCE at start (overlaps everything); C prefetched into H
// region for the y-dot; shf16 fp16 [t][130]; single paired MMA pass.
// ---------------------------------------------------------------------------
#define P3_W0 0
#define P3_W1 32768
#define P3_H  65536
#define P3_F  81920
#define P3FS  130
#define P3S   132
#define P3_Y  (81920 + 64 * P3FS * 2)
#define SMEM3_BYTES (P3_Y + 1024)

__global__ __launch_bounds__(256, 2)
void pass3_mma(const float* __restrict__ x,
               float* __restrict__ out)
{
    extern __shared__ unsigned char smraw[];
    const uint32_t sbase = smem_u32(smraw);
    __half* shf16 = (__half*)(smraw + P3_F);   // [t][130]
    float* sy  = (float*)(smraw + P3_Y);
    float* sh0 = sy + 64;
    float* sx0 = sh0 + 128;
    const int c = blockIdx.x, b = blockIdx.y, tid = threadIdx.x;
    const int wid = tid >> 5, lane = tid & 31;
    const size_t tbase = (size_t)b * NT + (size_t)c * CK;
    const size_t gbase = tbase * NS;

    // G1: prefetch C tile (16KB fp16 [t][s]) into H region
    {
        const unsigned char* srcC = (const unsigned char*)(g_C + gbase);
#pragma unroll
        for (int j = 0; j < 4; ++j) {
            int idx = tid + 256 * j;
            cp_async16(sbase + P3_H + (uint32_t)idx * 16, srcC + (size_t)idx * 16);
        }
        CP_COMMIT();
    }
    // G2: stage W_out hi+lo (64KB) — overlaps Loop1/y-dot/Loop2
    {
#pragma unroll
        for (int j = 0; j < 16; ++j) {
            int idx = tid + 256 * j;     // 4096 x 16B
            cp_async16(sbase + P3_W0 + (uint32_t)idx * 16,
                       g_Wb + (size_t)3 * 65536 + (size_t)idx * 16);
        }
        CP_COMMIT();
    }
    if (tid < 128) sh0[tid] = g_h0[((size_t)b * NC + c) * NS + tid];
    else if (tid < 192) sx0[tid - 128] = x[(tbase + tid - 128) * ND];
    __syncthreads();

    // Loop1: h = hl + p*h0 -> shf16[t][130] (fp16; coalesced [s][t] reads)
    {
        const size_t pb = (((size_t)b * NC + c) * NS) * (size_t)CK;
#pragma unroll
        for (int j = 0; j < 16; ++j) {
            int idx = tid + 256 * j;          // 4096 half2
            int s = idx >> 5, tp = idx & 31;
            int t0 = tp * 2;
            float2 pv = __half22float2(*(const __half2*)&g_p [pb + (size_t)s * CK + t0]);
            float2 hv = __half22float2(*(const __half2*)&g_hl[pb + (size_t)s * CK + t0]);
            float h0s = sh0[s];
            shf16[t0 * P3FS + s]       = __float2half(fmaf(pv.x, h0s, hv.x));
            shf16[(t0 + 1) * P3FS + s] = __float2half(fmaf(pv.y, h0s, hv.y));
        }
    }
    CP_WAIT(1); __syncthreads();

    // y[t] = sum_s C[t][s]*h[t][s]  (C + h both fp16 in smem)
    {
        const __half* sC = (const __half*)(smraw + P3_H);
        for (int t = wid * 8; t < wid * 8 + 8; ++t) {
            float v = 0.0f;
#pragma unroll
            for (int q = 0; q < 2; ++q) {
                int s = 2 * lane + 64 * q;
                float2 cf = __half22float2(*(const __half2*)&sC[t * NS + s]);
                float2 hf = __half22float2(*(const __half2*)&shf16[t * P3FS + s]);
                v = fmaf(cf.x, hf.x, v);
                v = fmaf(cf.y, hf.y, v);
            }
#pragma unroll
            for (int o = 16; o; o >>= 1) v += __shfl_xor_sync(0xFFFFFFFFu, v, o);
            if (lane == 0) sy[t] = v;
        }
    }
    __syncthreads();   // C reads done -> H region reusable

    // Loop2: shf16 -> fp16 swizzled tile in H region (token-row x s-k)
    {
        unsigned char* sH = smraw + P3_H;
#pragma unroll
        for (int j = 0; j < 32; ++j) {
            int idx = tid + 256 * j;          // 8192 elements
            int t = idx >> 7, s = idx & 127;
            __half h = shf16[t * P3FS + s];
            int half = s >> 6, kl = s & 63;
            uint32_t off = (uint32_t)(t * 128) + (((uint32_t)kl * 2) ^ ((uint32_t)(t & 7) << 4));
            *(__half*)(sH + half * 8192 + off) = h;
        }
    }
    CP_WAIT(0); __syncthreads();

    // Single paired MMA pass: D[d][t] = (W_hi + W_lo) h^T
    const int d0 = wid * 16;
    const uint32_t ar = lane & 7, aj = lane >> 3;
    const uint32_t a_rb  = (uint32_t)(d0 + (aj & 1) * 8 + ar) * 128;
    const uint32_t a_k16 = (aj >> 1) * 16;
    const uint32_t a_xor = ar << 4;
    const uint32_t b_row = lane & 7, b_j = lane >> 3;
    const uint32_t b_off = (b_j >> 1) * 1024 + b_row * 128;
    const uint32_t b_k16 = (b_j & 1) * 16;
    const uint32_t b_xor = b_row << 4;

    float acc[8][4];
#pragma unroll
    for (int nt = 0; nt < 8; ++nt)
#pragma unroll
        for (int q = 0; q < 4; ++q) acc[nt][q] = 0.0f;

#pragma unroll
    for (int kt = 0; kt < 8; ++kt) {
        const uint32_t half = kt >> 2;
        const uint32_t klo2 = (kt & 3) * 32;
        const uint32_t xb = sbase + P3_H + half * 8192;
        const uint32_t wa = half * 16384 + a_rb + ((klo2 + a_k16) ^ a_xor);
        uint32_t a0[4], a1[4];
        ldsm_x4(a0, sbase + P3_W0 + wa);
        ldsm_x4(a1, sbase + P3_W1 + wa);
#pragma unroll
        for (int i = 0; i < 4; ++i) {
            uint32_t bfr[4];
            ldsm_x4(bfr, xb + i * 2048 + b_off + ((klo2 + b_k16) ^ b_xor));
            mma_f16(acc[2 * i],     a0, &bfr[0]);
            mma_f16(acc[2 * i + 1], a0, &bfr[2]);
            mma_f16(acc[2 * i],     a1, &bfr[0]);
            mma_f16(acc[2 * i + 1], a1, &bfr[2]);
        }
    }
    __syncthreads();             // W/H reads done -> regions reusable for out

    // fragments -> sOut[t][132] overlaying W regions
    {
        float* sOut = (float*)smraw;
        const int dr = lane >> 2, dc = (lane & 3) * 2;
        const int d = d0 + dr;
#pragma unroll
        for (int nt = 0; nt < 8; ++nt) {
            const int t0 = nt * 8 + dc;
            sOut[t0 * P3S + d]           = acc[nt][0];
            sOut[(t0 + 1) * P3S + d]     = acc[nt][1];
            sOut[t0 * P3S + d + 8]       = acc[nt][2];
            sOut[(t0 + 1) * P3S + d + 8] = acc[nt][3];
        }
    }
    __syncthreads();

    // Epilogue: out = staged + y[t]*x[t,0], coalesced float4
    {
        const float* sOut = (const float*)smraw;
        float4* og = (float4*)(out + gbase);
#pragma unroll
        for (int j = 0; j < 8; ++j) {
            int i4 = tid + 256 * j;          // 2048 float4
            int t = i4 >> 5, d4 = i4 & 31;
            float4 v = *(const float4*)&sOut[t * P3S + d4 * 4];
            float yv = sy[t] * sx0[t];
            v.x += yv; v.y += yv; v.z += yv; v.w += yv;
            og[i4] = v;
        }
    }
}

// ---------------------------------------------------------------------------
extern "C" void kernel_launch(void* const* d_in, const int* in_sizes, int n_in,
                              void* d_out, int out_size)
{
    const float* x     = (const float*)d_in[0];
    const float* log_A = (const float*)d_in[1];
    const float* W_B   = (const float*)d_in[2];
    const float* W_C   = (const float*)d_in[3];
    const float* W_dt  = (const float*)d_in[4];
    const float* b_dt  = (const float*)d_in[5];
    const float* W_out = (const float*)d_in[6];
    float* out = (float*)d_out;

    cudaFuncSetAttribute(pass1_mma, cudaFuncAttributeMaxDynamicSharedMemorySize, SMEM1_BYTES);
    cudaFuncSetAttribute(pass2_kernel, cudaFuncAttributeMaxDynamicSharedMemorySize, SMEM2_BYTES);
    cudaFuncSetAttribute(pass3_mma, cudaFuncAttributeMaxDynamicSharedMemorySize, SMEM3_BYTES);

    prep_kernel<<<256, 256>>>(W_B, W_C, W_dt, W_out);
    pass1_mma<<<dim3(NC, NB), 256, SMEM1_BYTES>>>(x, log_A, b_dt);
    pass2_kernel<<<NB, 128, SMEM2_BYTES>>>();
    pass3_mma<<<dim3(NC, NB), 256, SMEM3_BYTES>>>(x, out);
}